// round 1
// baseline (speedup 1.0000x reference)
#include <cuda_runtime.h>
#include <math.h>

#define NN 50000
#define EE 800000
#define ET 850000          // EE + NN self loops
#define FIN 256
#define H1DIM 256          // HEADS*HID
#define HEADS 4
#define HID 64
#define ODIM 32
#define NEG 0.2f

// ---------------- scratch (device globals; no allocs allowed) ----------------
__device__ float g_h1[NN * H1DIM];     // x @ W1
__device__ float g_out1[NN * H1DIM];   // layer1 output (post ELU)
__device__ float g_h2[NN * ODIM];      // out1 @ W2
__device__ float g_as1[NN * HEADS];
__device__ float g_ad1[NN * HEADS];
__device__ float g_as2[NN];
__device__ float g_ad2[NN];
__device__ int   g_rowptr[NN + 1];
__device__ int   g_cnt[NN];
__device__ int   g_col[ET];

// ---------------- CSR build ----------------
__global__ void init_cnt_kernel() {
    int i = blockIdx.x * blockDim.x + threadIdx.x;
    if (i < NN) g_cnt[i] = 1;   // reserve slot 0 of each row for the self loop
}

__global__ void count_kernel(const int* __restrict__ dst) {
    int e = blockIdx.x * blockDim.x + threadIdx.x;
    if (e < EE) atomicAdd(&g_cnt[dst[e]], 1);
}

// single-block exclusive scan of g_cnt -> g_rowptr
__global__ void scan_kernel() {
    __shared__ int warpsum[32];
    __shared__ int s_carry;
    int t = threadIdx.x, lane = t & 31, w = t >> 5;
    if (t == 0) s_carry = 0;
    __syncthreads();
    for (int base = 0; base < NN; base += 1024) {
        int i = base + t;
        int v = (i < NN) ? g_cnt[i] : 0;
        int x = v;
        #pragma unroll
        for (int o = 1; o < 32; o <<= 1) {
            int y = __shfl_up_sync(0xffffffffu, x, o);
            if (lane >= o) x += y;
        }
        if (lane == 31) warpsum[w] = x;
        __syncthreads();
        if (w == 0) {
            int s = warpsum[lane];
            #pragma unroll
            for (int o = 1; o < 32; o <<= 1) {
                int y = __shfl_up_sync(0xffffffffu, s, o);
                if (lane >= o) s += y;
            }
            warpsum[lane] = s;
        }
        __syncthreads();
        int incl = x + (w > 0 ? warpsum[w - 1] : 0) + s_carry;
        if (i < NN) g_rowptr[i] = incl - v;   // exclusive
        __syncthreads();
        if (t == 1023) s_carry = incl;
        __syncthreads();
    }
    if (t == 0) g_rowptr[NN] = s_carry;       // == ET
}

__global__ void selfloop_kernel() {
    int i = blockIdx.x * blockDim.x + threadIdx.x;
    if (i < NN) {
        int r = g_rowptr[i];
        g_col[r] = i;          // self loop first
        g_cnt[i] = r + 1;      // cursor for scatter
    }
}

__global__ void scatter_kernel(const int* __restrict__ src, const int* __restrict__ dst) {
    int e = blockIdx.x * blockDim.x + threadIdx.x;
    if (e < EE) {
        int d = dst[e];
        int p = atomicAdd(&g_cnt[d], 1);
        g_col[p] = src[e];
    }
}

// ---------------- GEMM1: h1 = x[NN,256] @ W1[256,256] ----------------
// 128x128 tile, BK=16, 256 threads, 8x8 per thread
__global__ void gemm1_kernel(const float* __restrict__ A, const float* __restrict__ B) {
    __shared__ float sA[16][128];
    __shared__ float sB[16][128];
    int t = threadIdx.x;
    int tx = t & 15, ty = t >> 4;
    int row0 = blockIdx.y * 128, col0 = blockIdx.x * 128;

    float acc[8][8];
    #pragma unroll
    for (int i = 0; i < 8; i++)
        #pragma unroll
        for (int j = 0; j < 8; j++) acc[i][j] = 0.f;

    int aRow  = t >> 2;          // 0..63
    int aCol4 = (t & 3) * 4;     // 0,4,8,12
    int bRow  = t >> 5;          // 0..7
    int bCol4 = (t & 31) * 4;    // 0..124

    for (int k0 = 0; k0 < 256; k0 += 16) {
        #pragma unroll
        for (int i = 0; i < 2; i++) {
            int r  = aRow + i * 64;
            int gr = row0 + r;
            float4 v = make_float4(0.f, 0.f, 0.f, 0.f);
            if (gr < NN) v = *(const float4*)(A + (size_t)gr * 256 + k0 + aCol4);
            sA[aCol4 + 0][r] = v.x; sA[aCol4 + 1][r] = v.y;
            sA[aCol4 + 2][r] = v.z; sA[aCol4 + 3][r] = v.w;
        }
        #pragma unroll
        for (int i = 0; i < 2; i++) {
            int r = bRow + i * 8;
            *(float4*)(&sB[r][bCol4]) = *(const float4*)(B + (size_t)(k0 + r) * 256 + col0 + bCol4);
        }
        __syncthreads();
        #pragma unroll
        for (int kk = 0; kk < 16; kk++) {
            float a[8], b[8];
            *(float4*)(a)     = *(float4*)(&sA[kk][ty * 8]);
            *(float4*)(a + 4) = *(float4*)(&sA[kk][ty * 8 + 4]);
            *(float4*)(b)     = *(float4*)(&sB[kk][tx * 8]);
            *(float4*)(b + 4) = *(float4*)(&sB[kk][tx * 8 + 4]);
            #pragma unroll
            for (int i = 0; i < 8; i++)
                #pragma unroll
                for (int j = 0; j < 8; j++) acc[i][j] += a[i] * b[j];
        }
        __syncthreads();
    }
    #pragma unroll
    for (int i = 0; i < 8; i++) {
        int r = row0 + ty * 8 + i;
        if (r < NN) {
            #pragma unroll
            for (int j = 0; j < 8; j += 4) {
                float4 v = make_float4(acc[i][j], acc[i][j+1], acc[i][j+2], acc[i][j+3]);
                *(float4*)(g_h1 + (size_t)r * 256 + col0 + tx * 8 + j) = v;
            }
        }
    }
}

// ---------------- alpha1: per-node dots with a_src1/a_dst1 (warp per node) ----------------
__global__ void alpha1_kernel(const float* __restrict__ asrc, const float* __restrict__ adst) {
    int warp = (blockIdx.x * blockDim.x + threadIdx.x) >> 5;
    int lane = threadIdx.x & 31;
    if (warp >= NN) return;
    const float* hrow = g_h1 + (size_t)warp * 256 + lane * 8;
    float4 v1 = *(const float4*)(hrow);
    float4 v2 = *(const float4*)(hrow + 4);
    float4 s1 = *(const float4*)(asrc + lane * 8);
    float4 s2 = *(const float4*)(asrc + lane * 8 + 4);
    float4 d1 = *(const float4*)(adst + lane * 8);
    float4 d2 = *(const float4*)(adst + lane * 8 + 4);
    float ps = v1.x*s1.x + v1.y*s1.y + v1.z*s1.z + v1.w*s1.w
             + v2.x*s2.x + v2.y*s2.y + v2.z*s2.z + v2.w*s2.w;
    float pd = v1.x*d1.x + v1.y*d1.y + v1.z*d1.z + v1.w*d1.w
             + v2.x*d2.x + v2.y*d2.y + v2.z*d2.z + v2.w*d2.w;
    #pragma unroll
    for (int o = 1; o < 8; o <<= 1) {
        ps += __shfl_xor_sync(0xffffffffu, ps, o);
        pd += __shfl_xor_sync(0xffffffffu, pd, o);
    }
    if ((lane & 7) == 0) {
        g_as1[warp * 4 + (lane >> 3)] = ps;
        g_ad1[warp * 4 + (lane >> 3)] = pd;
    }
}

__device__ __forceinline__ float lrelu(float e) { return e >= 0.f ? e : NEG * e; }

// ---------------- layer1 softmax + aggregate + bias + ELU (warp per dst) ----------------
__global__ void agg1_kernel(const float* __restrict__ b1) {
    int n    = (blockIdx.x * blockDim.x + threadIdx.x) >> 5;
    int lane = threadIdx.x & 31;
    if (n >= NN) return;
    int beg = g_rowptr[n], end = g_rowptr[n + 1];
    float4 ad = *(const float4*)(g_ad1 + n * 4);

    // pass 1: per-head max
    float4 mx = make_float4(-1e30f, -1e30f, -1e30f, -1e30f);
    for (int j = beg + lane; j < end; j += 32) {
        int s = g_col[j];
        float4 as = *(const float4*)(g_as1 + s * 4);
        mx.x = fmaxf(mx.x, lrelu(as.x + ad.x));
        mx.y = fmaxf(mx.y, lrelu(as.y + ad.y));
        mx.z = fmaxf(mx.z, lrelu(as.z + ad.z));
        mx.w = fmaxf(mx.w, lrelu(as.w + ad.w));
    }
    #pragma unroll
    for (int o = 16; o; o >>= 1) {
        mx.x = fmaxf(mx.x, __shfl_xor_sync(0xffffffffu, mx.x, o));
        mx.y = fmaxf(mx.y, __shfl_xor_sync(0xffffffffu, mx.y, o));
        mx.z = fmaxf(mx.z, __shfl_xor_sync(0xffffffffu, mx.z, o));
        mx.w = fmaxf(mx.w, __shfl_xor_sync(0xffffffffu, mx.w, o));
    }
    // pass 2: denom
    float4 dn = make_float4(0.f, 0.f, 0.f, 0.f);
    for (int j = beg + lane; j < end; j += 32) {
        int s = g_col[j];
        float4 as = *(const float4*)(g_as1 + s * 4);
        dn.x += __expf(lrelu(as.x + ad.x) - mx.x);
        dn.y += __expf(lrelu(as.y + ad.y) - mx.y);
        dn.z += __expf(lrelu(as.z + ad.z) - mx.z);
        dn.w += __expf(lrelu(as.w + ad.w) - mx.w);
    }
    #pragma unroll
    for (int o = 16; o; o >>= 1) {
        dn.x += __shfl_xor_sync(0xffffffffu, dn.x, o);
        dn.y += __shfl_xor_sync(0xffffffffu, dn.y, o);
        dn.z += __shfl_xor_sync(0xffffffffu, dn.z, o);
        dn.w += __shfl_xor_sync(0xffffffffu, dn.w, o);
    }
    // per-lane head params (lane handles features lane*8 .. lane*8+7, head = lane>>3)
    int h = lane >> 3;
    float mh = (h == 0) ? mx.x : (h == 1) ? mx.y : (h == 2) ? mx.z : mx.w;
    float dh = (h == 0) ? dn.x : (h == 1) ? dn.y : (h == 2) ? dn.z : dn.w;
    float ah = (h == 0) ? ad.x : (h == 1) ? ad.y : (h == 2) ? ad.z : ad.w;
    float ih = 1.0f / (dh + 1e-16f);

    float acc[8];
    #pragma unroll
    for (int i = 0; i < 8; i++) acc[i] = 0.f;

    // pass 3: weighted accumulation (whole warp cooperates per edge)
    for (int j = beg; j < end; j++) {
        int s = g_col[j];
        float asv = g_as1[s * 4 + h];                     // broadcast within 8-lane groups
        float alpha = __expf(lrelu(asv + ah) - mh) * ih;
        const float* hs = g_h1 + (size_t)s * 256 + lane * 8;
        float4 u1 = *(const float4*)(hs);
        float4 u2 = *(const float4*)(hs + 4);
        acc[0] += alpha * u1.x; acc[1] += alpha * u1.y;
        acc[2] += alpha * u1.z; acc[3] += alpha * u1.w;
        acc[4] += alpha * u2.x; acc[5] += alpha * u2.y;
        acc[6] += alpha * u2.z; acc[7] += alpha * u2.w;
    }
    float4 bb1 = *(const float4*)(b1 + lane * 8);
    float4 bb2 = *(const float4*)(b1 + lane * 8 + 4);
    float o0 = acc[0] + bb1.x, o1 = acc[1] + bb1.y, o2 = acc[2] + bb1.z, o3 = acc[3] + bb1.w;
    float o4 = acc[4] + bb2.x, o5 = acc[5] + bb2.y, o6 = acc[6] + bb2.z, o7 = acc[7] + bb2.w;
    // ELU
    o0 = o0 > 0.f ? o0 : expm1f(o0);  o1 = o1 > 0.f ? o1 : expm1f(o1);
    o2 = o2 > 0.f ? o2 : expm1f(o2);  o3 = o3 > 0.f ? o3 : expm1f(o3);
    o4 = o4 > 0.f ? o4 : expm1f(o4);  o5 = o5 > 0.f ? o5 : expm1f(o5);
    o6 = o6 > 0.f ? o6 : expm1f(o6);  o7 = o7 > 0.f ? o7 : expm1f(o7);
    float* op = g_out1 + (size_t)n * 256 + lane * 8;
    *(float4*)(op)     = make_float4(o0, o1, o2, o3);
    *(float4*)(op + 4) = make_float4(o4, o5, o6, o7);
}

// ---------------- GEMM2: h2 = out1[NN,256] @ W2[256,32] ----------------
__global__ void gemm2_kernel(const float* __restrict__ B) {
    __shared__ float sW[256 * 32];    // full W2, 32KB
    __shared__ float sA[64][32];
    int t = threadIdx.x;
    for (int i = t; i < 2048; i += 256)
        ((float4*)sW)[i] = ((const float4*)B)[i];
    __syncthreads();

    int row0 = blockIdx.x * 64;
    int c  = t & 31;
    int rg = t >> 5;  // 0..7
    float acc[8];
    #pragma unroll
    for (int i = 0; i < 8; i++) acc[i] = 0.f;

    for (int k0 = 0; k0 < 256; k0 += 32) {
        __syncthreads();
        #pragma unroll
        for (int i = 0; i < 2; i++) {
            int idx = t + i * 256;        // 0..511 (float4 index)
            int r  = idx >> 3;            // 8 float4 per row
            int k4 = (idx & 7) * 4;
            int gr = row0 + r;
            float4 v = make_float4(0.f, 0.f, 0.f, 0.f);
            if (gr < NN) v = *(const float4*)(g_out1 + (size_t)gr * 256 + k0 + k4);
            *(float4*)(&sA[r][k4]) = v;
        }
        __syncthreads();
        #pragma unroll
        for (int kk = 0; kk < 32; kk++) {
            float b = sW[(k0 + kk) * 32 + c];
            #pragma unroll
            for (int i = 0; i < 8; i++)
                acc[i] += sA[rg * 8 + i][kk] * b;
        }
    }
    #pragma unroll
    for (int i = 0; i < 8; i++) {
        int r = row0 + rg * 8 + i;
        if (r < NN) g_h2[r * 32 + c] = acc[i];
    }
}

// ---------------- alpha2: warp per node ----------------
__global__ void alpha2_kernel(const float* __restrict__ asrc, const float* __restrict__ adst) {
    int n    = (blockIdx.x * blockDim.x + threadIdx.x) >> 5;
    int lane = threadIdx.x & 31;
    if (n >= NN) return;
    float v = g_h2[n * 32 + lane];
    float ps = v * asrc[lane];
    float pd = v * adst[lane];
    #pragma unroll
    for (int o = 16; o; o >>= 1) {
        ps += __shfl_xor_sync(0xffffffffu, ps, o);
        pd += __shfl_xor_sync(0xffffffffu, pd, o);
    }
    if (lane == 0) { g_as2[n] = ps; g_ad2[n] = pd; }
}

// ---------------- layer2 softmax + aggregate + bias (warp per dst) ----------------
__global__ void agg2_kernel(const float* __restrict__ b2, float* __restrict__ out) {
    int n    = (blockIdx.x * blockDim.x + threadIdx.x) >> 5;
    int lane = threadIdx.x & 31;
    if (n >= NN) return;
    int beg = g_rowptr[n], end = g_rowptr[n + 1];
    float ad = g_ad2[n];

    float mx = -1e30f;
    for (int j = beg + lane; j < end; j += 32)
        mx = fmaxf(mx, lrelu(g_as2[g_col[j]] + ad));
    #pragma unroll
    for (int o = 16; o; o >>= 1) mx = fmaxf(mx, __shfl_xor_sync(0xffffffffu, mx, o));

    float dn = 0.f;
    for (int j = beg + lane; j < end; j += 32)
        dn += __expf(lrelu(g_as2[g_col[j]] + ad) - mx);
    #pragma unroll
    for (int o = 16; o; o >>= 1) dn += __shfl_xor_sync(0xffffffffu, dn, o);
    float ih = 1.0f / (dn + 1e-16f);

    float acc = 0.f;
    for (int j = beg; j < end; j++) {
        int s = g_col[j];
        float alpha = __expf(lrelu(g_as2[s] + ad) - mx) * ih;
        acc += alpha * g_h2[s * 32 + lane];
    }
    out[n * 32 + lane] = acc + b2[lane];
}

// ---------------- launch ----------------
extern "C" void kernel_launch(void* const* d_in, const int* in_sizes, int n_in,
                              void* d_out, int out_size) {
    const float* x   = (const float*)d_in[0];
    const int*   ei  = (const int*)  d_in[1];
    const float* W1  = (const float*)d_in[2];
    const float* as1 = (const float*)d_in[3];
    const float* ad1 = (const float*)d_in[4];
    const float* b1  = (const float*)d_in[5];
    const float* W2  = (const float*)d_in[6];
    const float* as2 = (const float*)d_in[7];
    const float* ad2 = (const float*)d_in[8];
    const float* b2  = (const float*)d_in[9];
    float* out = (float*)d_out;

    const int* src = ei;
    const int* dst = ei + EE;

    init_cnt_kernel<<<(NN + 255) / 256, 256>>>();
    count_kernel<<<(EE + 255) / 256, 256>>>(dst);
    scan_kernel<<<1, 1024>>>();
    selfloop_kernel<<<(NN + 255) / 256, 256>>>();
    scatter_kernel<<<(EE + 255) / 256, 256>>>(src, dst);

    dim3 g1(2, 391);
    gemm1_kernel<<<g1, 256>>>(x, W1);

    int warp_blocks = (NN * 32 + 255) / 256;
    alpha1_kernel<<<warp_blocks, 256>>>(as1, ad1);
    agg1_kernel<<<warp_blocks, 256>>>(b1);

    gemm2_kernel<<<(NN + 63) / 64, 256>>>(W2);
    alpha2_kernel<<<warp_blocks, 256>>>(as2, ad2);
    agg2_kernel<<<warp_blocks, 256>>>(b2, out);
}

// round 3
// speedup vs baseline: 1.1134x; 1.1134x over previous
#include <cuda_runtime.h>
#include <math.h>

#define NN 50000
#define EE 800000
#define ET 850000          // EE + NN self loops
#define FIN 256
#define H1DIM 256          // HEADS*HID
#define HEADS 4
#define HID 64
#define ODIM 32
#define NEG 0.2f

// ---------------- scratch (device globals; no allocs allowed) ----------------
__device__ float g_h1[NN * H1DIM];     // x @ W1
__device__ float g_out1[NN * H1DIM];   // layer1 output (post ELU)
__device__ float g_h2[NN * ODIM];      // out1 @ W2
__device__ float g_as1[NN * HEADS];
__device__ float g_ad1[NN * HEADS];
__device__ float g_as2[NN];
__device__ float g_ad2[NN];
__device__ int   g_rowptr[NN + 1];
__device__ int   g_cnt[NN];
__device__ int   g_col[ET];
__device__ int   g_bsum[256];

// ---------------- f32x2 helpers ----------------
typedef unsigned long long ull;

__device__ __forceinline__ ull f32x2_dup(float x) {
    ull r;
    asm("mov.b64 %0, {%1, %1};" : "=l"(r) : "f"(x));
    return r;
}
__device__ __forceinline__ void ffma2(ull& d, ull a, ull b) {
    asm("fma.rn.f32x2 %0, %1, %2, %3;" : "=l"(d) : "l"(a), "l"(b), "l"(d));
}

// ---------------- CSR build ----------------
__global__ void init_cnt_kernel() {
    int i = blockIdx.x * blockDim.x + threadIdx.x;
    if (i < NN) g_cnt[i] = 1;   // reserve slot 0 of each row for the self loop
}

__global__ void count_kernel(const int* __restrict__ dst) {
    int e = blockIdx.x * blockDim.x + threadIdx.x;
    if (e < EE) atomicAdd(&g_cnt[dst[e]], 1);
}

// two-level scan: scan1 (per-block exclusive + block sums), scan2 (scan of
// block sums), scan3 (add offsets)
__global__ void scan1_kernel() {
    __shared__ int ws[8];
    int i = blockIdx.x * 256 + threadIdx.x;
    int lane = threadIdx.x & 31, w = threadIdx.x >> 5;
    int v = (i < NN) ? g_cnt[i] : 0;
    int x = v;
    #pragma unroll
    for (int o = 1; o < 32; o <<= 1) {
        int y = __shfl_up_sync(0xffffffffu, x, o);
        if (lane >= o) x += y;
    }
    if (lane == 31) ws[w] = x;
    __syncthreads();
    if (w == 0 && lane < 8) {
        int s = ws[lane];
        #pragma unroll
        for (int o = 1; o < 8; o <<= 1) {
            int y = __shfl_up_sync(0x000000ffu, s, o);
            if (lane >= o) s += y;
        }
        ws[lane] = s;
    }
    __syncthreads();
    int incl = x + (w > 0 ? ws[w - 1] : 0);
    if (i < NN) g_rowptr[i] = incl - v;   // block-local exclusive
    if (threadIdx.x == 255) g_bsum[blockIdx.x] = incl;
}

__global__ void scan2_kernel(int nb) {   // 1 block, 256 threads
    __shared__ int ws[8];
    int t = threadIdx.x, lane = t & 31, w = t >> 5;
    int v = (t < nb) ? g_bsum[t] : 0;
    int x = v;
    #pragma unroll
    for (int o = 1; o < 32; o <<= 1) {
        int y = __shfl_up_sync(0xffffffffu, x, o);
        if (lane >= o) x += y;
    }
    if (lane == 31) ws[w] = x;
    __syncthreads();
    if (w == 0 && lane < 8) {
        int s = ws[lane];
        #pragma unroll
        for (int o = 1; o < 8; o <<= 1) {
            int y = __shfl_up_sync(0x000000ffu, s, o);
            if (lane >= o) s += y;
        }
        ws[lane] = s;
    }
    __syncthreads();
    int incl = x + (w > 0 ? ws[w - 1] : 0);
    if (t < nb) g_bsum[t] = incl - v;     // exclusive offsets
    if (t == nb - 1) g_rowptr[NN] = incl; // total == ET
}

__global__ void scan3_kernel() {
    int i = blockIdx.x * 256 + threadIdx.x;
    if (i < NN) g_rowptr[i] += g_bsum[i >> 8];
}

__global__ void selfloop_kernel() {
    int i = blockIdx.x * blockDim.x + threadIdx.x;
    if (i < NN) {
        int r = g_rowptr[i];
        g_col[r] = i;          // self loop first
        g_cnt[i] = r + 1;      // cursor for scatter
    }
}

__global__ void scatter_kernel(const int* __restrict__ src, const int* __restrict__ dst) {
    int e = blockIdx.x * blockDim.x + threadIdx.x;
    if (e < EE) {
        int d = dst[e];
        int p = atomicAdd(&g_cnt[d], 1);
        g_col[p] = src[e];
    }
}

// ---------------- GEMM1: h1 = x[NN,256] @ W1[256,256] ----------------
// 128x128 tile, BK=16, 256 threads, 8x8 per thread, f32x2 packed FMA
__global__ void gemm1_kernel(const float* __restrict__ A, const float* __restrict__ B) {
    __shared__ float sA[16][128];
    __shared__ float sB[16][128];
    int t = threadIdx.x;
    int tx = t & 15, ty = t >> 4;
    int row0 = blockIdx.y * 128, col0 = blockIdx.x * 128;

    ull acc[8][4];
    #pragma unroll
    for (int i = 0; i < 8; i++)
        #pragma unroll
        for (int j = 0; j < 4; j++) acc[i][j] = 0ULL;

    int aRow  = t >> 2;          // 0..63
    int aCol4 = (t & 3) * 4;     // 0,4,8,12
    int bRow  = t >> 5;          // 0..7
    int bCol4 = (t & 31) * 4;    // 0..124

    for (int k0 = 0; k0 < 256; k0 += 16) {
        #pragma unroll
        for (int i = 0; i < 2; i++) {
            int r  = aRow + i * 64;
            int gr = row0 + r;
            float4 v = make_float4(0.f, 0.f, 0.f, 0.f);
            if (gr < NN) v = *(const float4*)(A + (size_t)gr * 256 + k0 + aCol4);
            sA[aCol4 + 0][r] = v.x; sA[aCol4 + 1][r] = v.y;
            sA[aCol4 + 2][r] = v.z; sA[aCol4 + 3][r] = v.w;
        }
        #pragma unroll
        for (int i = 0; i < 2; i++) {
            int r = bRow + i * 8;
            *(float4*)(&sB[r][bCol4]) = *(const float4*)(B + (size_t)(k0 + r) * 256 + col0 + bCol4);
        }
        __syncthreads();
        #pragma unroll
        for (int kk = 0; kk < 16; kk++) {
            float a[8];
            union { float4 v[2]; ull p[4]; } bu;
            *(float4*)(a)     = *(float4*)(&sA[kk][ty * 8]);
            *(float4*)(a + 4) = *(float4*)(&sA[kk][ty * 8 + 4]);
            bu.v[0] = *(float4*)(&sB[kk][tx * 8]);
            bu.v[1] = *(float4*)(&sB[kk][tx * 8 + 4]);
            #pragma unroll
            for (int i = 0; i < 8; i++) {
                ull ad = f32x2_dup(a[i]);
                #pragma unroll
                for (int jp = 0; jp < 4; jp++) ffma2(acc[i][jp], ad, bu.p[jp]);
            }
        }
        __syncthreads();
    }
    #pragma unroll
    for (int i = 0; i < 8; i++) {
        int r = row0 + ty * 8 + i;
        if (r < NN) {
            union { ull p[2]; float4 v; } o0, o1;
            o0.p[0] = acc[i][0]; o0.p[1] = acc[i][1];
            o1.p[0] = acc[i][2]; o1.p[1] = acc[i][3];
            *(float4*)(g_h1 + (size_t)r * 256 + col0 + tx * 8)     = o0.v;
            *(float4*)(g_h1 + (size_t)r * 256 + col0 + tx * 8 + 4) = o1.v;
        }
    }
}

// ---------------- alpha1: per-node dots with a_src1/a_dst1 (warp per node) ----------------
__global__ void alpha1_kernel(const float* __restrict__ asrc, const float* __restrict__ adst) {
    int warp = (blockIdx.x * blockDim.x + threadIdx.x) >> 5;
    int lane = threadIdx.x & 31;
    if (warp >= NN) return;
    const float* hrow = g_h1 + (size_t)warp * 256 + lane * 8;
    float4 v1 = *(const float4*)(hrow);
    float4 v2 = *(const float4*)(hrow + 4);
    float4 s1 = *(const float4*)(asrc + lane * 8);
    float4 s2 = *(const float4*)(asrc + lane * 8 + 4);
    float4 d1 = *(const float4*)(adst + lane * 8);
    float4 d2 = *(const float4*)(adst + lane * 8 + 4);
    float ps = v1.x*s1.x + v1.y*s1.y + v1.z*s1.z + v1.w*s1.w
             + v2.x*s2.x + v2.y*s2.y + v2.z*s2.z + v2.w*s2.w;
    float pd = v1.x*d1.x + v1.y*d1.y + v1.z*d1.z + v1.w*d1.w
             + v2.x*d2.x + v2.y*d2.y + v2.z*d2.z + v2.w*d2.w;
    #pragma unroll
    for (int o = 1; o < 8; o <<= 1) {
        ps += __shfl_xor_sync(0xffffffffu, ps, o);
        pd += __shfl_xor_sync(0xffffffffu, pd, o);
    }
    if ((lane & 7) == 0) {
        g_as1[warp * 4 + (lane >> 3)] = ps;
        g_ad1[warp * 4 + (lane >> 3)] = pd;
    }
}

__device__ __forceinline__ float lrelu(float e) { return e >= 0.f ? e : NEG * e; }

// ---------------- layer1 softmax + aggregate + bias + ELU (warp per dst) ----------------
__global__ void agg1_kernel(const float* __restrict__ b1) {
    int n    = (blockIdx.x * blockDim.x + threadIdx.x) >> 5;
    int lane = threadIdx.x & 31;
    if (n >= NN) return;
    int beg = g_rowptr[n], end = g_rowptr[n + 1];
    float4 ad = *(const float4*)(g_ad1 + n * 4);

    // pass 1: per-head max
    float4 mx = make_float4(-1e30f, -1e30f, -1e30f, -1e30f);
    for (int j = beg + lane; j < end; j += 32) {
        int s = g_col[j];
        float4 as = *(const float4*)(g_as1 + s * 4);
        mx.x = fmaxf(mx.x, lrelu(as.x + ad.x));
        mx.y = fmaxf(mx.y, lrelu(as.y + ad.y));
        mx.z = fmaxf(mx.z, lrelu(as.z + ad.z));
        mx.w = fmaxf(mx.w, lrelu(as.w + ad.w));
    }
    #pragma unroll
    for (int o = 16; o; o >>= 1) {
        mx.x = fmaxf(mx.x, __shfl_xor_sync(0xffffffffu, mx.x, o));
        mx.y = fmaxf(mx.y, __shfl_xor_sync(0xffffffffu, mx.y, o));
        mx.z = fmaxf(mx.z, __shfl_xor_sync(0xffffffffu, mx.z, o));
        mx.w = fmaxf(mx.w, __shfl_xor_sync(0xffffffffu, mx.w, o));
    }
    // pass 2: denom
    float4 dn = make_float4(0.f, 0.f, 0.f, 0.f);
    for (int j = beg + lane; j < end; j += 32) {
        int s = g_col[j];
        float4 as = *(const float4*)(g_as1 + s * 4);
        dn.x += __expf(lrelu(as.x + ad.x) - mx.x);
        dn.y += __expf(lrelu(as.y + ad.y) - mx.y);
        dn.z += __expf(lrelu(as.z + ad.z) - mx.z);
        dn.w += __expf(lrelu(as.w + ad.w) - mx.w);
    }
    #pragma unroll
    for (int o = 16; o; o >>= 1) {
        dn.x += __shfl_xor_sync(0xffffffffu, dn.x, o);
        dn.y += __shfl_xor_sync(0xffffffffu, dn.y, o);
        dn.z += __shfl_xor_sync(0xffffffffu, dn.z, o);
        dn.w += __shfl_xor_sync(0xffffffffu, dn.w, o);
    }
    // per-lane head params (lane handles features lane*8 .. lane*8+7, head = lane>>3)
    int h = lane >> 3;
    float mh = (h == 0) ? mx.x : (h == 1) ? mx.y : (h == 2) ? mx.z : mx.w;
    float dh = (h == 0) ? dn.x : (h == 1) ? dn.y : (h == 2) ? dn.z : dn.w;
    float ah = (h == 0) ? ad.x : (h == 1) ? ad.y : (h == 2) ? ad.z : ad.w;
    float ih = 1.0f / (dh + 1e-16f);

    float acc[8];
    #pragma unroll
    for (int i = 0; i < 8; i++) acc[i] = 0.f;

    // pass 3: weighted accumulation (whole warp cooperates per edge)
    for (int j = beg; j < end; j++) {
        int s = g_col[j];
        float asv = g_as1[s * 4 + h];                     // broadcast within 8-lane groups
        float alpha = __expf(lrelu(asv + ah) - mh) * ih;
        const float* hs = g_h1 + (size_t)s * 256 + lane * 8;
        float4 u1 = *(const float4*)(hs);
        float4 u2 = *(const float4*)(hs + 4);
        acc[0] += alpha * u1.x; acc[1] += alpha * u1.y;
        acc[2] += alpha * u1.z; acc[3] += alpha * u1.w;
        acc[4] += alpha * u2.x; acc[5] += alpha * u2.y;
        acc[6] += alpha * u2.z; acc[7] += alpha * u2.w;
    }
    float4 bb1 = *(const float4*)(b1 + lane * 8);
    float4 bb2 = *(const float4*)(b1 + lane * 8 + 4);
    float o0 = acc[0] + bb1.x, o1 = acc[1] + bb1.y, o2 = acc[2] + bb1.z, o3 = acc[3] + bb1.w;
    float o4 = acc[4] + bb2.x, o5 = acc[5] + bb2.y, o6 = acc[6] + bb2.z, o7 = acc[7] + bb2.w;
    // ELU
    o0 = o0 > 0.f ? o0 : expm1f(o0);  o1 = o1 > 0.f ? o1 : expm1f(o1);
    o2 = o2 > 0.f ? o2 : expm1f(o2);  o3 = o3 > 0.f ? o3 : expm1f(o3);
    o4 = o4 > 0.f ? o4 : expm1f(o4);  o5 = o5 > 0.f ? o5 : expm1f(o5);
    o6 = o6 > 0.f ? o6 : expm1f(o6);  o7 = o7 > 0.f ? o7 : expm1f(o7);
    float* op = g_out1 + (size_t)n * 256 + lane * 8;
    *(float4*)(op)     = make_float4(o0, o1, o2, o3);
    *(float4*)(op + 4) = make_float4(o4, o5, o6, o7);
}

// ---------------- GEMM2: h2 = out1[NN,256] @ W2[256,32] ----------------
__global__ void gemm2_kernel(const float* __restrict__ B) {
    __shared__ float sW[256 * 32];    // full W2, 32KB
    __shared__ float sA[64][32];
    int t = threadIdx.x;
    for (int i = t; i < 2048; i += 256)
        ((float4*)sW)[i] = ((const float4*)B)[i];
    __syncthreads();

    int row0 = blockIdx.x * 64;
    int c  = t & 31;
    int rg = t >> 5;  // 0..7
    float acc[8];
    #pragma unroll
    for (int i = 0; i < 8; i++) acc[i] = 0.f;

    for (int k0 = 0; k0 < 256; k0 += 32) {
        __syncthreads();
        #pragma unroll
        for (int i = 0; i < 2; i++) {
            int idx = t + i * 256;        // 0..511 (float4 index)
            int r  = idx >> 3;            // 8 float4 per row
            int k4 = (idx & 7) * 4;
            int gr = row0 + r;
            float4 v = make_float4(0.f, 0.f, 0.f, 0.f);
            if (gr < NN) v = *(const float4*)(g_out1 + (size_t)gr * 256 + k0 + k4);
            *(float4*)(&sA[r][k4]) = v;
        }
        __syncthreads();
        #pragma unroll
        for (int kk = 0; kk < 32; kk++) {
            float b = sW[(k0 + kk) * 32 + c];
            #pragma unroll
            for (int i = 0; i < 8; i++)
                acc[i] += sA[rg * 8 + i][kk] * b;
        }
    }
    #pragma unroll
    for (int i = 0; i < 8; i++) {
        int r = row0 + rg * 8 + i;
        if (r < NN) g_h2[r * 32 + c] = acc[i];
    }
}

// ---------------- alpha2: warp per node ----------------
__global__ void alpha2_kernel(const float* __restrict__ asrc, const float* __restrict__ adst) {
    int n    = (blockIdx.x * blockDim.x + threadIdx.x) >> 5;
    int lane = threadIdx.x & 31;
    if (n >= NN) return;
    float v = g_h2[n * 32 + lane];
    float ps = v * asrc[lane];
    float pd = v * adst[lane];
    #pragma unroll
    for (int o = 16; o; o >>= 1) {
        ps += __shfl_xor_sync(0xffffffffu, ps, o);
        pd += __shfl_xor_sync(0xffffffffu, pd, o);
    }
    if (lane == 0) { g_as2[n] = ps; g_ad2[n] = pd; }
}

// ---------------- layer2 softmax + aggregate + bias (warp per dst) ----------------
__global__ void agg2_kernel(const float* __restrict__ b2, float* __restrict__ out) {
    int n    = (blockIdx.x * blockDim.x + threadIdx.x) >> 5;
    int lane = threadIdx.x & 31;
    if (n >= NN) return;
    int beg = g_rowptr[n], end = g_rowptr[n + 1];
    float ad = g_ad2[n];

    float mx = -1e30f;
    for (int j = beg + lane; j < end; j += 32)
        mx = fmaxf(mx, lrelu(g_as2[g_col[j]] + ad));
    #pragma unroll
    for (int o = 16; o; o >>= 1) mx = fmaxf(mx, __shfl_xor_sync(0xffffffffu, mx, o));

    float dn = 0.f;
    for (int j = beg + lane; j < end; j += 32)
        dn += __expf(lrelu(g_as2[g_col[j]] + ad) - mx);
    #pragma unroll
    for (int o = 16; o; o >>= 1) dn += __shfl_xor_sync(0xffffffffu, dn, o);
    float ih = 1.0f / (dn + 1e-16f);

    float acc = 0.f;
    for (int j = beg; j < end; j++) {
        int s = g_col[j];
        float alpha = __expf(lrelu(g_as2[s] + ad) - mx) * ih;
        acc += alpha * g_h2[s * 32 + lane];
    }
    out[n * 32 + lane] = acc + b2[lane];
}

// ---------------- launch ----------------
extern "C" void kernel_launch(void* const* d_in, const int* in_sizes, int n_in,
                              void* d_out, int out_size) {
    const float* x   = (const float*)d_in[0];
    const int*   ei  = (const int*)  d_in[1];
    const float* W1  = (const float*)d_in[2];
    const float* as1 = (const float*)d_in[3];
    const float* ad1 = (const float*)d_in[4];
    const float* b1  = (const float*)d_in[5];
    const float* W2  = (const float*)d_in[6];
    const float* as2 = (const float*)d_in[7];
    const float* ad2 = (const float*)d_in[8];
    const float* b2  = (const float*)d_in[9];
    float* out = (float*)d_out;

    const int* src = ei;
    const int* dst = ei + EE;

    int nb = (NN + 255) / 256;   // 196

    init_cnt_kernel<<<nb, 256>>>();
    count_kernel<<<(EE + 255) / 256, 256>>>(dst);
    scan1_kernel<<<nb, 256>>>();
    scan2_kernel<<<1, 256>>>(nb);
    scan3_kernel<<<nb, 256>>>();
    selfloop_kernel<<<nb, 256>>>();
    scatter_kernel<<<(EE + 255) / 256, 256>>>(src, dst);

    dim3 g1(2, 391);
    gemm1_kernel<<<g1, 256>>>(x, W1);

    int warp_blocks = (NN * 32 + 255) / 256;
    alpha1_kernel<<<warp_blocks, 256>>>(as1, ad1);
    agg1_kernel<<<warp_blocks, 256>>>(b1);

    gemm2_kernel<<<(NN + 63) / 64, 256>>>(W2);
    alpha2_kernel<<<warp_blocks, 256>>>(as2, ad2);
    agg2_kernel<<<warp_blocks, 256>>>(b2, out);
}

// round 5
// speedup vs baseline: 1.5385x; 1.3819x over previous
#include <cuda_runtime.h>
#include <math.h>
#include <cstdint>

#define NN 50000
#define EE 800000
#define ET 850000          // EE + NN self loops
#define FIN 256
#define H1DIM 256          // HEADS*HID
#define HEADS 4
#define HID 64
#define ODIM 32
#define NEG 0.2f

// ---------------- scratch (device globals; no allocs allowed) ----------------
__device__ float g_h1[NN * H1DIM];     // x @ W1
__device__ float g_out1[NN * H1DIM];   // layer1 output (post ELU)
__device__ float g_h2[NN * ODIM];      // out1 @ W2
__device__ float g_W1T[H1DIM * FIN];   // W1 transposed, tf32-rounded: [n][k]
__device__ float g_as1[NN * HEADS];
__device__ float g_ad1[NN * HEADS];
__device__ float g_as2[NN];
__device__ float g_ad2[NN];
__device__ int   g_rowptr[NN + 1];
__device__ int   g_cnt[NN];
__device__ int   g_col[ET];
__device__ int   g_bsum[256];

__device__ __forceinline__ uint32_t tf32_rna(float x) {
    uint32_t r;
    asm("cvt.rna.tf32.f32 %0, %1;" : "=r"(r) : "f"(x));
    return r;
}

// ---------------- CSR build ----------------
__global__ void init_cnt_kernel() {
    int i = blockIdx.x * blockDim.x + threadIdx.x;
    if (i < NN) g_cnt[i] = 1;   // reserve slot 0 of each row for the self loop
}

__global__ void count_kernel(const int* __restrict__ dst) {
    int e = blockIdx.x * blockDim.x + threadIdx.x;
    if (e < EE) atomicAdd(&g_cnt[dst[e]], 1);
}

__global__ void scan1_kernel() {
    __shared__ int ws[8];
    int i = blockIdx.x * 256 + threadIdx.x;
    int lane = threadIdx.x & 31, w = threadIdx.x >> 5;
    int v = (i < NN) ? g_cnt[i] : 0;
    int x = v;
    #pragma unroll
    for (int o = 1; o < 32; o <<= 1) {
        int y = __shfl_up_sync(0xffffffffu, x, o);
        if (lane >= o) x += y;
    }
    if (lane == 31) ws[w] = x;
    __syncthreads();
    if (w == 0 && lane < 8) {
        int s = ws[lane];
        #pragma unroll
        for (int o = 1; o < 8; o <<= 1) {
            int y = __shfl_up_sync(0x000000ffu, s, o);
            if (lane >= o) s += y;
        }
        ws[lane] = s;
    }
    __syncthreads();
    int incl = x + (w > 0 ? ws[w - 1] : 0);
    if (i < NN) g_rowptr[i] = incl - v;   // block-local exclusive
    if (threadIdx.x == 255) g_bsum[blockIdx.x] = incl;
}

__global__ void scan2_kernel(int nb) {   // 1 block, 256 threads
    __shared__ int ws[8];
    int t = threadIdx.x, lane = t & 31, w = t >> 5;
    int v = (t < nb) ? g_bsum[t] : 0;
    int x = v;
    #pragma unroll
    for (int o = 1; o < 32; o <<= 1) {
        int y = __shfl_up_sync(0xffffffffu, x, o);
        if (lane >= o) x += y;
    }
    if (lane == 31) ws[w] = x;
    __syncthreads();
    if (w == 0 && lane < 8) {
        int s = ws[lane];
        #pragma unroll
        for (int o = 1; o < 8; o <<= 1) {
            int y = __shfl_up_sync(0x000000ffu, s, o);
            if (lane >= o) s += y;
        }
        ws[lane] = s;
    }
    __syncthreads();
    int incl = x + (w > 0 ? ws[w - 1] : 0);
    if (t < nb) g_bsum[t] = incl - v;     // exclusive offsets
    if (t == nb - 1) g_rowptr[NN] = incl; // total == ET
}

__global__ void scan3_kernel() {
    int i = blockIdx.x * 256 + threadIdx.x;
    if (i < NN) g_rowptr[i] += g_bsum[i >> 8];
}

__global__ void selfloop_kernel() {
    int i = blockIdx.x * blockDim.x + threadIdx.x;
    if (i < NN) {
        int r = g_rowptr[i];
        g_col[r] = i;          // self loop first
        g_cnt[i] = r + 1;      // cursor for scatter
    }
}

__global__ void scatter_kernel(const int* __restrict__ src, const int* __restrict__ dst) {
    int e = blockIdx.x * blockDim.x + threadIdx.x;
    if (e < EE) {
        int d = dst[e];
        int p = atomicAdd(&g_cnt[d], 1);
        g_col[p] = src[e];
    }
}

// ---------------- W1 transpose + tf32 round: g_W1T[n][k] = tf32(W1[k][n]) ----------------
__global__ void w1t_kernel(const float* __restrict__ W1) {
    int i = blockIdx.x * 256 + threadIdx.x;   // output index n*256+k
    int n = i >> 8, k = i & 255;
    uint32_t t = tf32_rna(W1[k * 256 + n]);
    g_W1T[i] = __uint_as_float(t);
}

// ---------------- GEMM1 (mma.sync tf32): h1 = x[NN,256] @ W1[256,256] ----------------
// BM=128, BN=128, BK=16. 8 warps: 4 (m) x 2 (n), warp tile 32x64.
// SMEM row stride padded to 20 floats -> fragment banks = 4r+c (conflict-free),
// 80B row stride keeps float4 stores 16B-aligned.
#define G1_STRIDE 20

__device__ __forceinline__ void mma_tf32(float* c, const uint32_t* a, const uint32_t* b) {
    asm volatile(
        "mma.sync.aligned.m16n8k8.row.col.f32.tf32.tf32.f32 "
        "{%0,%1,%2,%3}, {%4,%5,%6,%7}, {%8,%9}, {%0,%1,%2,%3};"
        : "+f"(c[0]), "+f"(c[1]), "+f"(c[2]), "+f"(c[3])
        : "r"(a[0]), "r"(a[1]), "r"(a[2]), "r"(a[3]), "r"(b[0]), "r"(b[1]));
}

__global__ void __launch_bounds__(256) gemm1_mma_kernel(const float* __restrict__ x) {
    __shared__ float sA[2][128 * G1_STRIDE];
    __shared__ float sB[2][128 * G1_STRIDE];

    int tid  = threadIdx.x;
    int wid  = tid >> 5, lane = tid & 31;
    int qr   = lane >> 2, qc = lane & 3;
    int warpM = (wid & 3) * 32;
    int warpN = (wid >> 2) * 64;
    int row0 = blockIdx.x * 128, col0 = blockIdx.y * 128;

    float c[2][8][4];
    #pragma unroll
    for (int mt = 0; mt < 2; mt++)
        #pragma unroll
        for (int nt = 0; nt < 8; nt++)
            #pragma unroll
            for (int i = 0; i < 4; i++) c[mt][nt][i] = 0.f;

    // gmem load indices: 2 float4 each for A and B per iteration
    int lr  = tid >> 2;         // 0..63 -> row pairs
    int lk4 = (tid & 3) * 4;    // 0,4,8,12

    // prologue: load kt=0 into buffer 0
    {
        #pragma unroll
        for (int i = 0; i < 2; i++) {
            int r = lr + i * 64;
            int gr = row0 + r;
            float4 v = make_float4(0.f, 0.f, 0.f, 0.f);
            if (gr < NN) v = *(const float4*)(x + (size_t)gr * 256 + lk4);
            uint4 tv;
            tv.x = tf32_rna(v.x); tv.y = tf32_rna(v.y);
            tv.z = tf32_rna(v.z); tv.w = tf32_rna(v.w);
            *(uint4*)(&sA[0][r * G1_STRIDE + lk4]) = tv;
            float4 wv = *(const float4*)(g_W1T + (size_t)(col0 + r) * 256 + lk4);
            *(float4*)(&sB[0][r * G1_STRIDE + lk4]) = wv;
        }
    }
    __syncthreads();

    #pragma unroll 1
    for (int kt = 0; kt < 16; kt++) {
        int cur = kt & 1;
        float4 av[2], bv[2];
        if (kt < 15) {
            #pragma unroll
            for (int i = 0; i < 2; i++) {
                int r = lr + i * 64;
                int gr = row0 + r;
                av[i] = make_float4(0.f, 0.f, 0.f, 0.f);
                if (gr < NN) av[i] = *(const float4*)(x + (size_t)gr * 256 + (kt + 1) * 16 + lk4);
                bv[i] = *(const float4*)(g_W1T + (size_t)(col0 + r) * 256 + (kt + 1) * 16 + lk4);
            }
        }
        // compute current buffer: 2 ksteps of 8
        #pragma unroll
        for (int ks = 0; ks < 2; ks++) {
            int kb = ks * 8;
            uint32_t a[2][4], b[8][2];
            #pragma unroll
            for (int mt = 0; mt < 2; mt++) {
                int base = (warpM + mt * 16 + qr) * G1_STRIDE + kb + qc;
                a[mt][0] = __float_as_uint(sA[cur][base]);
                a[mt][1] = __float_as_uint(sA[cur][base + 8 * G1_STRIDE]);
                a[mt][2] = __float_as_uint(sA[cur][base + 4]);
                a[mt][3] = __float_as_uint(sA[cur][base + 8 * G1_STRIDE + 4]);
            }
            #pragma unroll
            for (int nt = 0; nt < 8; nt++) {
                int bb = (warpN + nt * 8 + qr) * G1_STRIDE + kb + qc;
                b[nt][0] = __float_as_uint(sB[cur][bb]);
                b[nt][1] = __float_as_uint(sB[cur][bb + 4]);
            }
            #pragma unroll
            for (int mt = 0; mt < 2; mt++)
                #pragma unroll
                for (int nt = 0; nt < 8; nt++)
                    mma_tf32(c[mt][nt], a[mt], b[nt]);
        }
        if (kt < 15) {
            int nxt = 1 - cur;
            #pragma unroll
            for (int i = 0; i < 2; i++) {
                int r = lr + i * 64;
                uint4 tv;
                tv.x = tf32_rna(av[i].x); tv.y = tf32_rna(av[i].y);
                tv.z = tf32_rna(av[i].z); tv.w = tf32_rna(av[i].w);
                *(uint4*)(&sA[nxt][r * G1_STRIDE + lk4]) = tv;
                *(float4*)(&sB[nxt][r * G1_STRIDE + lk4]) = bv[i];
            }
            __syncthreads();
        }
    }

    // epilogue
    #pragma unroll
    for (int mt = 0; mt < 2; mt++) {
        int r1 = row0 + warpM + mt * 16 + qr;
        int r2 = r1 + 8;
        #pragma unroll
        for (int nt = 0; nt < 8; nt++) {
            int cc = col0 + warpN + nt * 8 + qc * 2;
            if (r1 < NN) *(float2*)(g_h1 + (size_t)r1 * 256 + cc) = make_float2(c[mt][nt][0], c[mt][nt][1]);
            if (r2 < NN) *(float2*)(g_h1 + (size_t)r2 * 256 + cc) = make_float2(c[mt][nt][2], c[mt][nt][3]);
        }
    }
}

// ---------------- alpha1: per-node dots with a_src1/a_dst1 (warp per node) ----------------
__global__ void alpha1_kernel(const float* __restrict__ asrc, const float* __restrict__ adst) {
    int warp = (blockIdx.x * blockDim.x + threadIdx.x) >> 5;
    int lane = threadIdx.x & 31;
    if (warp >= NN) return;
    const float* hrow = g_h1 + (size_t)warp * 256 + lane * 8;
    float4 v1 = *(const float4*)(hrow);
    float4 v2 = *(const float4*)(hrow + 4);
    float4 s1 = *(const float4*)(asrc + lane * 8);
    float4 s2 = *(const float4*)(asrc + lane * 8 + 4);
    float4 d1 = *(const float4*)(adst + lane * 8);
    float4 d2 = *(const float4*)(adst + lane * 8 + 4);
    float ps = v1.x*s1.x + v1.y*s1.y + v1.z*s1.z + v1.w*s1.w
             + v2.x*s2.x + v2.y*s2.y + v2.z*s2.z + v2.w*s2.w;
    float pd = v1.x*d1.x + v1.y*d1.y + v1.z*d1.z + v1.w*d1.w
             + v2.x*d2.x + v2.y*d2.y + v2.z*d2.z + v2.w*d2.w;
    #pragma unroll
    for (int o = 1; o < 8; o <<= 1) {
        ps += __shfl_xor_sync(0xffffffffu, ps, o);
        pd += __shfl_xor_sync(0xffffffffu, pd, o);
    }
    if ((lane & 7) == 0) {
        g_as1[warp * 4 + (lane >> 3)] = ps;
        g_ad1[warp * 4 + (lane >> 3)] = pd;
    }
}

__device__ __forceinline__ float lrelu(float e) { return e >= 0.f ? e : NEG * e; }

// ---------------- layer1 softmax + aggregate + bias + ELU (warp per dst) ----------------
__global__ void agg1_kernel(const float* __restrict__ b1) {
    int n    = (blockIdx.x * blockDim.x + threadIdx.x) >> 5;
    int lane = threadIdx.x & 31;
    if (n >= NN) return;
    int beg = g_rowptr[n], end = g_rowptr[n + 1];
    float4 ad = *(const float4*)(g_ad1 + n * 4);

    // pass 1: per-head max
    float4 mx = make_float4(-1e30f, -1e30f, -1e30f, -1e30f);
    for (int j = beg + lane; j < end; j += 32) {
        int s = g_col[j];
        float4 as = *(const float4*)(g_as1 + s * 4);
        mx.x = fmaxf(mx.x, lrelu(as.x + ad.x));
        mx.y = fmaxf(mx.y, lrelu(as.y + ad.y));
        mx.z = fmaxf(mx.z, lrelu(as.z + ad.z));
        mx.w = fmaxf(mx.w, lrelu(as.w + ad.w));
    }
    #pragma unroll
    for (int o = 16; o; o >>= 1) {
        mx.x = fmaxf(mx.x, __shfl_xor_sync(0xffffffffu, mx.x, o));
        mx.y = fmaxf(mx.y, __shfl_xor_sync(0xffffffffu, mx.y, o));
        mx.z = fmaxf(mx.z, __shfl_xor_sync(0xffffffffu, mx.z, o));
        mx.w = fmaxf(mx.w, __shfl_xor_sync(0xffffffffu, mx.w, o));
    }
    // pass 2: denom
    float4 dn = make_float4(0.f, 0.f, 0.f, 0.f);
    for (int j = beg + lane; j < end; j += 32) {
        int s = g_col[j];
        float4 as = *(const float4*)(g_as1 + s * 4);
        dn.x += __expf(lrelu(as.x + ad.x) - mx.x);
        dn.y += __expf(lrelu(as.y + ad.y) - mx.y);
        dn.z += __expf(lrelu(as.z + ad.z) - mx.z);
        dn.w += __expf(lrelu(as.w + ad.w) - mx.w);
    }
    #pragma unroll
    for (int o = 16; o; o >>= 1) {
        dn.x += __shfl_xor_sync(0xffffffffu, dn.x, o);
        dn.y += __shfl_xor_sync(0xffffffffu, dn.y, o);
        dn.z += __shfl_xor_sync(0xffffffffu, dn.z, o);
        dn.w += __shfl_xor_sync(0xffffffffu, dn.w, o);
    }
    int h = lane >> 3;
    float mh = (h == 0) ? mx.x : (h == 1) ? mx.y : (h == 2) ? mx.z : mx.w;
    float dh = (h == 0) ? dn.x : (h == 1) ? dn.y : (h == 2) ? dn.z : dn.w;
    float ah = (h == 0) ? ad.x : (h == 1) ? ad.y : (h == 2) ? ad.z : ad.w;
    float ih = 1.0f / (dh + 1e-16f);

    float acc[8];
    #pragma unroll
    for (int i = 0; i < 8; i++) acc[i] = 0.f;

    for (int j = beg; j < end; j++) {
        int s = g_col[j];
        float asv = g_as1[s * 4 + h];
        float alpha = __expf(lrelu(asv + ah) - mh) * ih;
        const float* hs = g_h1 + (size_t)s * 256 + lane * 8;
        float4 u1 = *(const float4*)(hs);
        float4 u2 = *(const float4*)(hs + 4);
        acc[0] += alpha * u1.x; acc[1] += alpha * u1.y;
        acc[2] += alpha * u1.z; acc[3] += alpha * u1.w;
        acc[4] += alpha * u2.x; acc[5] += alpha * u2.y;
        acc[6] += alpha * u2.z; acc[7] += alpha * u2.w;
    }
    float4 bb1 = *(const float4*)(b1 + lane * 8);
    float4 bb2 = *(const float4*)(b1 + lane * 8 + 4);
    float o0 = acc[0] + bb1.x, o1 = acc[1] + bb1.y, o2 = acc[2] + bb1.z, o3 = acc[3] + bb1.w;
    float o4 = acc[4] + bb2.x, o5 = acc[5] + bb2.y, o6 = acc[6] + bb2.z, o7 = acc[7] + bb2.w;
    o0 = o0 > 0.f ? o0 : expm1f(o0);  o1 = o1 > 0.f ? o1 : expm1f(o1);
    o2 = o2 > 0.f ? o2 : expm1f(o2);  o3 = o3 > 0.f ? o3 : expm1f(o3);
    o4 = o4 > 0.f ? o4 : expm1f(o4);  o5 = o5 > 0.f ? o5 : expm1f(o5);
    o6 = o6 > 0.f ? o6 : expm1f(o6);  o7 = o7 > 0.f ? o7 : expm1f(o7);
    float* op = g_out1 + (size_t)n * 256 + lane * 8;
    *(float4*)(op)     = make_float4(o0, o1, o2, o3);
    *(float4*)(op + 4) = make_float4(o4, o5, o6, o7);
}

// ---------------- GEMM2: h2 = out1[NN,256] @ W2[256,32] ----------------
__global__ void gemm2_kernel(const float* __restrict__ B) {
    __shared__ float sW[256 * 32];    // full W2, 32KB
    __shared__ float sA[64][32];
    int t = threadIdx.x;
    for (int i = t; i < 2048; i += 256)
        ((float4*)sW)[i] = ((const float4*)B)[i];
    __syncthreads();

    int row0 = blockIdx.x * 64;
    int c  = t & 31;
    int rg = t >> 5;  // 0..7
    float acc[8];
    #pragma unroll
    for (int i = 0; i < 8; i++) acc[i] = 0.f;

    for (int k0 = 0; k0 < 256; k0 += 32) {
        __syncthreads();
        #pragma unroll
        for (int i = 0; i < 2; i++) {
            int idx = t + i * 256;        // 0..511 (float4 index)
            int r  = idx >> 3;            // 8 float4 per row
            int k4 = (idx & 7) * 4;
            int gr = row0 + r;
            float4 v = make_float4(0.f, 0.f, 0.f, 0.f);
            if (gr < NN) v = *(const float4*)(g_out1 + (size_t)gr * 256 + k0 + k4);
            *(float4*)(&sA[r][k4]) = v;
        }
        __syncthreads();
        #pragma unroll
        for (int kk = 0; kk < 32; kk++) {
            float b = sW[(k0 + kk) * 32 + c];
            #pragma unroll
            for (int i = 0; i < 8; i++)
                acc[i] += sA[rg * 8 + i][kk] * b;
        }
    }
    #pragma unroll
    for (int i = 0; i < 8; i++) {
        int r = row0 + rg * 8 + i;
        if (r < NN) g_h2[r * 32 + c] = acc[i];
    }
}

// ---------------- alpha2: warp per node ----------------
__global__ void alpha2_kernel(const float* __restrict__ asrc, const float* __restrict__ adst) {
    int n    = (blockIdx.x * blockDim.x + threadIdx.x) >> 5;
    int lane = threadIdx.x & 31;
    if (n >= NN) return;
    float v = g_h2[n * 32 + lane];
    float ps = v * asrc[lane];
    float pd = v * adst[lane];
    #pragma unroll
    for (int o = 16; o; o >>= 1) {
        ps += __shfl_xor_sync(0xffffffffu, ps, o);
        pd += __shfl_xor_sync(0xffffffffu, pd, o);
    }
    if (lane == 0) { g_as2[n] = ps; g_ad2[n] = pd; }
}

// ---------------- layer2 softmax + aggregate + bias (warp per dst) ----------------
__global__ void agg2_kernel(const float* __restrict__ b2, float* __restrict__ out) {
    int n    = (blockIdx.x * blockDim.x + threadIdx.x) >> 5;
    int lane = threadIdx.x & 31;
    if (n >= NN) return;
    int beg = g_rowptr[n], end = g_rowptr[n + 1];
    float ad = g_ad2[n];

    float mx = -1e30f;
    for (int j = beg + lane; j < end; j += 32)
        mx = fmaxf(mx, lrelu(g_as2[g_col[j]] + ad));
    #pragma unroll
    for (int o = 16; o; o >>= 1) mx = fmaxf(mx, __shfl_xor_sync(0xffffffffu, mx, o));

    float dn = 0.f;
    for (int j = beg + lane; j < end; j += 32)
        dn += __expf(lrelu(g_as2[g_col[j]] + ad) - mx);
    #pragma unroll
    for (int o = 16; o; o >>= 1) dn += __shfl_xor_sync(0xffffffffu, dn, o);
    float ih = 1.0f / (dn + 1e-16f);

    float acc = 0.f;
    for (int j = beg; j < end; j++) {
        int s = g_col[j];
        float alpha = __expf(lrelu(g_as2[s] + ad) - mx) * ih;
        acc += alpha * g_h2[s * 32 + lane];
    }
    out[n * 32 + lane] = acc + b2[lane];
}

// ---------------- launch ----------------
extern "C" void kernel_launch(void* const* d_in, const int* in_sizes, int n_in,
                              void* d_out, int out_size) {
    const float* x   = (const float*)d_in[0];
    const int*   ei  = (const int*)  d_in[1];
    const float* W1  = (const float*)d_in[2];
    const float* as1 = (const float*)d_in[3];
    const float* ad1 = (const float*)d_in[4];
    const float* b1  = (const float*)d_in[5];
    const float* W2  = (const float*)d_in[6];
    const float* as2 = (const float*)d_in[7];
    const float* ad2 = (const float*)d_in[8];
    const float* b2  = (const float*)d_in[9];
    float* out = (float*)d_out;

    const int* src = ei;
    const int* dst = ei + EE;

    int nb = (NN + 255) / 256;   // 196

    init_cnt_kernel<<<nb, 256>>>();
    count_kernel<<<(EE + 255) / 256, 256>>>(dst);
    scan1_kernel<<<nb, 256>>>();
    scan2_kernel<<<1, 256>>>(nb);
    scan3_kernel<<<nb, 256>>>();
    selfloop_kernel<<<nb, 256>>>();
    scatter_kernel<<<(EE + 255) / 256, 256>>>(src, dst);

    w1t_kernel<<<256, 256>>>(W1);
    dim3 g1((NN + 127) / 128, 2);
    gemm1_mma_kernel<<<g1, 256>>>(x);

    int warp_blocks = (NN * 32 + 255) / 256;
    alpha1_kernel<<<warp_blocks, 256>>>(as1, ad1);
    agg1_kernel<<<warp_blocks, 256>>>(b1);

    gemm2_kernel<<<(NN + 63) / 64, 256>>>(W2);
    alpha2_kernel<<<warp_blocks, 256>>>(as2, ad2);
    agg2_kernel<<<warp_blocks, 256>>>(b2, out);
}

// round 6
// speedup vs baseline: 1.7262x; 1.1220x over previous
#include <cuda_runtime.h>
#include <math.h>
#include <cstdint>

#define NN 50000
#define EE 800000
#define ET 850000          // EE + NN self loops
#define FIN 256
#define H1DIM 256          // HEADS*HID
#define HEADS 4
#define HID 64
#define ODIM 32
#define NEG 0.2f

// ---------------- scratch (device globals; no allocs allowed) ----------------
__device__ float g_h1[NN * H1DIM];     // x @ W1
__device__ float g_out1[NN * H1DIM];   // layer1 output (post ELU)
__device__ float g_h2[NN * ODIM];      // out1 @ W2
__device__ float g_W1T[H1DIM * FIN];   // W1 transposed, tf32-rounded: [n][k]
__device__ float g_as1[NN * HEADS];
__device__ float g_ad1[NN * HEADS];
__device__ float g_as2[NN];
__device__ float g_ad2[NN];
__device__ int   g_rowptr[NN + 1];
__device__ int   g_cnt[NN];
__device__ int   g_col[ET];
__device__ int   g_bsum[256];

typedef unsigned long long ull;

__device__ __forceinline__ uint32_t tf32_rna(float x) {
    uint32_t r;
    asm("cvt.rna.tf32.f32 %0, %1;" : "=r"(r) : "f"(x));
    return r;
}
__device__ __forceinline__ void ffma2(ull& d, ull a, ull b) {
    asm("fma.rn.f32x2 %0, %1, %2, %3;" : "=l"(d) : "l"(a), "l"(b), "l"(d));
}

// ---------------- CSR build ----------------
// merged: init g_cnt (blocks 0..195) + W1 transpose/tf32 (blocks 196..451)
__global__ void init_w1t_kernel(const float* __restrict__ W1) {
    int b = blockIdx.x;
    if (b < 196) {
        int i = b * 256 + threadIdx.x;
        if (i < NN) g_cnt[i] = 1;   // slot 0 of each row = self loop
    } else {
        int i = (b - 196) * 256 + threadIdx.x;   // 0..65535, n*256+k
        int n = i >> 8, k = i & 255;
        g_W1T[i] = __uint_as_float(tf32_rna(W1[k * 256 + n]));
    }
}

__global__ void count_kernel(const int* __restrict__ dst) {
    int e = blockIdx.x * blockDim.x + threadIdx.x;
    if (e < EE) atomicAdd(&g_cnt[dst[e]], 1);
}

__global__ void scan1_kernel() {
    __shared__ int ws[8];
    int i = blockIdx.x * 256 + threadIdx.x;
    int lane = threadIdx.x & 31, w = threadIdx.x >> 5;
    int v = (i < NN) ? g_cnt[i] : 0;
    int x = v;
    #pragma unroll
    for (int o = 1; o < 32; o <<= 1) {
        int y = __shfl_up_sync(0xffffffffu, x, o);
        if (lane >= o) x += y;
    }
    if (lane == 31) ws[w] = x;
    __syncthreads();
    if (w == 0 && lane < 8) {
        int s = ws[lane];
        #pragma unroll
        for (int o = 1; o < 8; o <<= 1) {
            int y = __shfl_up_sync(0x000000ffu, s, o);
            if (lane >= o) s += y;
        }
        ws[lane] = s;
    }
    __syncthreads();
    int incl = x + (w > 0 ? ws[w - 1] : 0);
    if (i < NN) g_rowptr[i] = incl - v;   // block-local exclusive
    if (threadIdx.x == 255) g_bsum[blockIdx.x] = incl;
}

__global__ void scan2_kernel(int nb) {   // 1 block, 256 threads
    __shared__ int ws[8];
    int t = threadIdx.x, lane = t & 31, w = t >> 5;
    int v = (t < nb) ? g_bsum[t] : 0;
    int x = v;
    #pragma unroll
    for (int o = 1; o < 32; o <<= 1) {
        int y = __shfl_up_sync(0xffffffffu, x, o);
        if (lane >= o) x += y;
    }
    if (lane == 31) ws[w] = x;
    __syncthreads();
    if (w == 0 && lane < 8) {
        int s = ws[lane];
        #pragma unroll
        for (int o = 1; o < 8; o <<= 1) {
            int y = __shfl_up_sync(0x000000ffu, s, o);
            if (lane >= o) s += y;
        }
        ws[lane] = s;
    }
    __syncthreads();
    int incl = x + (w > 0 ? ws[w - 1] : 0);
    if (t < nb) g_bsum[t] = incl - v;     // exclusive offsets
    if (t == nb - 1) g_rowptr[NN] = incl; // total == ET
}

// merged scan3 + selfloop
__global__ void scan3self_kernel() {
    int i = blockIdx.x * 256 + threadIdx.x;
    if (i < NN) {
        int r = g_rowptr[i] + g_bsum[i >> 8];
        g_rowptr[i] = r;
        g_col[r] = i;          // self loop first
        g_cnt[i] = r + 1;      // cursor for scatter
    }
}

__global__ void scatter_kernel(const int* __restrict__ src, const int* __restrict__ dst) {
    int e = blockIdx.x * blockDim.x + threadIdx.x;
    if (e < EE) {
        int d = dst[e];
        int p = atomicAdd(&g_cnt[d], 1);
        g_col[p] = src[e];
    }
}

// ---------------- GEMM1 (mma.sync tf32) + fused alpha1 ----------------
// BM=128, BN=128, BK=16. 8 warps: 4 (m) x 2 (n), warp tile 32x64 = one head.
#define G1_STRIDE 20

__device__ __forceinline__ void mma_tf32(float* c, const uint32_t* a, const uint32_t* b) {
    asm volatile(
        "mma.sync.aligned.m16n8k8.row.col.f32.tf32.tf32.f32 "
        "{%0,%1,%2,%3}, {%4,%5,%6,%7}, {%8,%9}, {%0,%1,%2,%3};"
        : "+f"(c[0]), "+f"(c[1]), "+f"(c[2]), "+f"(c[3])
        : "r"(a[0]), "r"(a[1]), "r"(a[2]), "r"(a[3]), "r"(b[0]), "r"(b[1]));
}

__global__ void __launch_bounds__(256) gemm1_mma_kernel(const float* __restrict__ x,
                                                        const float* __restrict__ as1,
                                                        const float* __restrict__ ad1) {
    __shared__ float sA[2][128 * G1_STRIDE];
    __shared__ float sB[2][128 * G1_STRIDE];

    int tid  = threadIdx.x;
    int wid  = tid >> 5, lane = tid & 31;
    int qr   = lane >> 2, qc = lane & 3;
    int warpM = (wid & 3) * 32;
    int warpN = (wid >> 2) * 64;
    int row0 = blockIdx.x * 128, col0 = blockIdx.y * 128;

    float c[2][8][4];
    #pragma unroll
    for (int mt = 0; mt < 2; mt++)
        #pragma unroll
        for (int nt = 0; nt < 8; nt++)
            #pragma unroll
            for (int i = 0; i < 4; i++) c[mt][nt][i] = 0.f;

    int lr  = tid >> 2;         // 0..63
    int lk4 = (tid & 3) * 4;    // 0,4,8,12

    {
        #pragma unroll
        for (int i = 0; i < 2; i++) {
            int r = lr + i * 64;
            int gr = row0 + r;
            float4 v = make_float4(0.f, 0.f, 0.f, 0.f);
            if (gr < NN) v = *(const float4*)(x + (size_t)gr * 256 + lk4);
            uint4 tv;
            tv.x = tf32_rna(v.x); tv.y = tf32_rna(v.y);
            tv.z = tf32_rna(v.z); tv.w = tf32_rna(v.w);
            *(uint4*)(&sA[0][r * G1_STRIDE + lk4]) = tv;
            float4 wv = *(const float4*)(g_W1T + (size_t)(col0 + r) * 256 + lk4);
            *(float4*)(&sB[0][r * G1_STRIDE + lk4]) = wv;
        }
    }
    __syncthreads();

    #pragma unroll 1
    for (int kt = 0; kt < 16; kt++) {
        int cur = kt & 1;
        float4 av[2], bv[2];
        if (kt < 15) {
            #pragma unroll
            for (int i = 0; i < 2; i++) {
                int r = lr + i * 64;
                int gr = row0 + r;
                av[i] = make_float4(0.f, 0.f, 0.f, 0.f);
                if (gr < NN) av[i] = *(const float4*)(x + (size_t)gr * 256 + (kt + 1) * 16 + lk4);
                bv[i] = *(const float4*)(g_W1T + (size_t)(col0 + r) * 256 + (kt + 1) * 16 + lk4);
            }
        }
        #pragma unroll
        for (int ks = 0; ks < 2; ks++) {
            int kb = ks * 8;
            uint32_t a[2][4], b[8][2];
            #pragma unroll
            for (int mt = 0; mt < 2; mt++) {
                int base = (warpM + mt * 16 + qr) * G1_STRIDE + kb + qc;
                a[mt][0] = __float_as_uint(sA[cur][base]);
                a[mt][1] = __float_as_uint(sA[cur][base + 8 * G1_STRIDE]);
                a[mt][2] = __float_as_uint(sA[cur][base + 4]);
                a[mt][3] = __float_as_uint(sA[cur][base + 8 * G1_STRIDE + 4]);
            }
            #pragma unroll
            for (int nt = 0; nt < 8; nt++) {
                int bb = (warpN + nt * 8 + qr) * G1_STRIDE + kb + qc;
                b[nt][0] = __float_as_uint(sB[cur][bb]);
                b[nt][1] = __float_as_uint(sB[cur][bb + 4]);
            }
            #pragma unroll
            for (int mt = 0; mt < 2; mt++)
                #pragma unroll
                for (int nt = 0; nt < 8; nt++)
                    mma_tf32(c[mt][nt], a[mt], b[nt]);
        }
        if (kt < 15) {
            int nxt = 1 - cur;
            #pragma unroll
            for (int i = 0; i < 2; i++) {
                int r = lr + i * 64;
                uint4 tv;
                tv.x = tf32_rna(av[i].x); tv.y = tf32_rna(av[i].y);
                tv.z = tf32_rna(av[i].z); tv.w = tf32_rna(av[i].w);
                *(uint4*)(&sA[nxt][r * G1_STRIDE + lk4]) = tv;
                *(float4*)(&sB[nxt][r * G1_STRIDE + lk4]) = bv[i];
            }
            __syncthreads();
        }
    }

    // epilogue: store h1
    #pragma unroll
    for (int mt = 0; mt < 2; mt++) {
        int r1 = row0 + warpM + mt * 16 + qr;
        int r2 = r1 + 8;
        #pragma unroll
        for (int nt = 0; nt < 8; nt++) {
            int cc = col0 + warpN + nt * 8 + qc * 2;
            if (r1 < NN) *(float2*)(g_h1 + (size_t)r1 * 256 + cc) = make_float2(c[mt][nt][0], c[mt][nt][1]);
            if (r2 < NN) *(float2*)(g_h1 + (size_t)r2 * 256 + cc) = make_float2(c[mt][nt][2], c[mt][nt][3]);
        }
    }

    // fused alpha1: warp tile covers exactly head h, cols h*64 .. h*64+63
    int h = blockIdx.y * 2 + (wid >> 2);
    float asv[16], adv[16];
    #pragma unroll
    for (int nt = 0; nt < 8; nt++)
        #pragma unroll
        for (int i = 0; i < 2; i++) {
            int cl = nt * 8 + qc * 2 + i;
            asv[nt * 2 + i] = as1[h * 64 + cl];
            adv[nt * 2 + i] = ad1[h * 64 + cl];
        }
    #pragma unroll
    for (int mt = 0; mt < 2; mt++) {
        float ps1 = 0.f, pd1 = 0.f, ps2 = 0.f, pd2 = 0.f;
        #pragma unroll
        for (int nt = 0; nt < 8; nt++) {
            ps1 += c[mt][nt][0] * asv[nt * 2] + c[mt][nt][1] * asv[nt * 2 + 1];
            pd1 += c[mt][nt][0] * adv[nt * 2] + c[mt][nt][1] * adv[nt * 2 + 1];
            ps2 += c[mt][nt][2] * asv[nt * 2] + c[mt][nt][3] * asv[nt * 2 + 1];
            pd2 += c[mt][nt][2] * adv[nt * 2] + c[mt][nt][3] * adv[nt * 2 + 1];
        }
        #pragma unroll
        for (int o = 1; o <= 2; o <<= 1) {
            ps1 += __shfl_xor_sync(0xffffffffu, ps1, o);
            pd1 += __shfl_xor_sync(0xffffffffu, pd1, o);
            ps2 += __shfl_xor_sync(0xffffffffu, ps2, o);
            pd2 += __shfl_xor_sync(0xffffffffu, pd2, o);
        }
        if (qc == 0) {
            int r1 = row0 + warpM + mt * 16 + qr, r2 = r1 + 8;
            if (r1 < NN) { g_as1[r1 * 4 + h] = ps1; g_ad1[r1 * 4 + h] = pd1; }
            if (r2 < NN) { g_as1[r2 * 4 + h] = ps2; g_ad1[r2 * 4 + h] = pd2; }
        }
    }
}

__device__ __forceinline__ float lrelu(float e) { return e >= 0.f ? e : NEG * e; }

// ---------------- layer1 softmax (no-max) + aggregate + bias + ELU ----------------
__global__ void agg1_kernel(const float* __restrict__ b1) {
    int n    = (blockIdx.x * blockDim.x + threadIdx.x) >> 5;
    int lane = threadIdx.x & 31;
    if (n >= NN) return;
    int beg = g_rowptr[n], end = g_rowptr[n + 1];
    float4 ad = *(const float4*)(g_ad1 + n * 4);

    // pass 1: denom (no max subtraction; |e| is small by construction)
    float4 dn = make_float4(0.f, 0.f, 0.f, 0.f);
    for (int j = beg + lane; j < end; j += 32) {
        int s = g_col[j];
        float4 as = *(const float4*)(g_as1 + s * 4);
        dn.x += __expf(lrelu(as.x + ad.x));
        dn.y += __expf(lrelu(as.y + ad.y));
        dn.z += __expf(lrelu(as.z + ad.z));
        dn.w += __expf(lrelu(as.w + ad.w));
    }
    #pragma unroll
    for (int o = 16; o; o >>= 1) {
        dn.x += __shfl_xor_sync(0xffffffffu, dn.x, o);
        dn.y += __shfl_xor_sync(0xffffffffu, dn.y, o);
        dn.z += __shfl_xor_sync(0xffffffffu, dn.z, o);
        dn.w += __shfl_xor_sync(0xffffffffu, dn.w, o);
    }
    int h = lane >> 3;
    float dh = (h == 0) ? dn.x : (h == 1) ? dn.y : (h == 2) ? dn.z : dn.w;
    float ah = (h == 0) ? ad.x : (h == 1) ? ad.y : (h == 2) ? ad.z : ad.w;
    float ih = 1.0f / (dh + 1e-16f);

    float acc[8];
    #pragma unroll
    for (int i = 0; i < 8; i++) acc[i] = 0.f;

    // pass 2: weighted accumulation
    for (int j = beg; j < end; j++) {
        int s = g_col[j];
        float asv = g_as1[s * 4 + h];
        float alpha = __expf(lrelu(asv + ah)) * ih;
        const float* hs = g_h1 + (size_t)s * 256 + lane * 8;
        float4 u1 = *(const float4*)(hs);
        float4 u2 = *(const float4*)(hs + 4);
        acc[0] += alpha * u1.x; acc[1] += alpha * u1.y;
        acc[2] += alpha * u1.z; acc[3] += alpha * u1.w;
        acc[4] += alpha * u2.x; acc[5] += alpha * u2.y;
        acc[6] += alpha * u2.z; acc[7] += alpha * u2.w;
    }
    float4 bb1 = *(const float4*)(b1 + lane * 8);
    float4 bb2 = *(const float4*)(b1 + lane * 8 + 4);
    float o0 = acc[0] + bb1.x, o1 = acc[1] + bb1.y, o2 = acc[2] + bb1.z, o3 = acc[3] + bb1.w;
    float o4 = acc[4] + bb2.x, o5 = acc[5] + bb2.y, o6 = acc[6] + bb2.z, o7 = acc[7] + bb2.w;
    o0 = o0 > 0.f ? o0 : expm1f(o0);  o1 = o1 > 0.f ? o1 : expm1f(o1);
    o2 = o2 > 0.f ? o2 : expm1f(o2);  o3 = o3 > 0.f ? o3 : expm1f(o3);
    o4 = o4 > 0.f ? o4 : expm1f(o4);  o5 = o5 > 0.f ? o5 : expm1f(o5);
    o6 = o6 > 0.f ? o6 : expm1f(o6);  o7 = o7 > 0.f ? o7 : expm1f(o7);
    float* op = g_out1 + (size_t)n * 256 + lane * 8;
    *(float4*)(op)     = make_float4(o0, o1, o2, o3);
    *(float4*)(op + 4) = make_float4(o4, o5, o6, o7);
}

// ---------------- GEMM2 (f32x2) + fused alpha2 ----------------
#define W2S 258
__global__ void gemm2_kernel(const float* __restrict__ B,
                             const float* __restrict__ asrc,
                             const float* __restrict__ adst) {
    __shared__ float sW[32 * W2S];    // W2 transposed: sW[c][k]
    __shared__ float sA[64][32];
    int t = threadIdx.x;
    for (int i = t; i < 8192; i += 256) {
        int c = i & 31, k = i >> 5;
        sW[c * W2S + k] = B[k * 32 + c];
    }
    __syncthreads();

    int row0 = blockIdx.x * 64;
    int lane = t & 31;
    int rg = t >> 5;  // 0..7
    float a2s = asrc[lane], a2d = adst[lane];
    ull acc2[8];
    #pragma unroll
    for (int i = 0; i < 8; i++) acc2[i] = 0ULL;

    for (int k0 = 0; k0 < 256; k0 += 32) {
        __syncthreads();
        #pragma unroll
        for (int i = 0; i < 2; i++) {
            int idx = t + i * 256;        // 0..511 (float4 index)
            int r  = idx >> 3;
            int k4 = (idx & 7) * 4;
            int gr = row0 + r;
            float4 v = make_float4(0.f, 0.f, 0.f, 0.f);
            if (gr < NN) v = *(const float4*)(g_out1 + (size_t)gr * 256 + k0 + k4);
            *(float4*)(&sA[r][k4]) = v;
        }
        __syncthreads();
        #pragma unroll
        for (int kk = 0; kk < 32; kk += 2) {
            ull b2 = *(const ull*)(&sW[lane * W2S + k0 + kk]);
            #pragma unroll
            for (int i = 0; i < 8; i++) {
                ull a2 = *(const ull*)(&sA[rg * 8 + i][kk]);
                ffma2(acc2[i], a2, b2);
            }
        }
    }
    #pragma unroll
    for (int i = 0; i < 8; i++) {
        int r = row0 + rg * 8 + i;
        float2 p = *(float2*)(&acc2[i]);
        float v = p.x + p.y;
        if (r < NN) g_h2[r * 32 + lane] = v;
        float ps = v * a2s, pd = v * a2d;
        #pragma unroll
        for (int o = 16; o; o >>= 1) {
            ps += __shfl_xor_sync(0xffffffffu, ps, o);
            pd += __shfl_xor_sync(0xffffffffu, pd, o);
        }
        if (lane == 0 && r < NN) { g_as2[r] = ps; g_ad2[r] = pd; }
    }
}

// ---------------- layer2 softmax (no-max) + aggregate + bias ----------------
__global__ void agg2_kernel(const float* __restrict__ b2, float* __restrict__ out) {
    int n    = (blockIdx.x * blockDim.x + threadIdx.x) >> 5;
    int lane = threadIdx.x & 31;
    if (n >= NN) return;
    int beg = g_rowptr[n], end = g_rowptr[n + 1];
    float ad = g_ad2[n];

    float dn = 0.f;
    for (int j = beg + lane; j < end; j += 32)
        dn += __expf(lrelu(g_as2[g_col[j]] + ad));
    #pragma unroll
    for (int o = 16; o; o >>= 1) dn += __shfl_xor_sync(0xffffffffu, dn, o);
    float ih = 1.0f / (dn + 1e-16f);

    float acc = 0.f;
    for (int j = beg; j < end; j++) {
        int s = g_col[j];
        float alpha = __expf(lrelu(g_as2[s] + ad)) * ih;
        acc += alpha * g_h2[s * 32 + lane];
    }
    out[n * 32 + lane] = acc + b2[lane];
}

// ---------------- launch ----------------
extern "C" void kernel_launch(void* const* d_in, const int* in_sizes, int n_in,
                              void* d_out, int out_size) {
    const float* x   = (const float*)d_in[0];
    const int*   ei  = (const int*)  d_in[1];
    const float* W1  = (const float*)d_in[2];
    const float* as1 = (const float*)d_in[3];
    const float* ad1 = (const float*)d_in[4];
    const float* b1  = (const float*)d_in[5];
    const float* W2  = (const float*)d_in[6];
    const float* as2 = (const float*)d_in[7];
    const float* ad2 = (const float*)d_in[8];
    const float* b2  = (const float*)d_in[9];
    float* out = (float*)d_out;

    const int* src = ei;
    const int* dst = ei + EE;

    int nb = (NN + 255) / 256;   // 196

    init_w1t_kernel<<<nb + 256, 256>>>(W1);
    count_kernel<<<(EE + 255) / 256, 256>>>(dst);
    scan1_kernel<<<nb, 256>>>();
    scan2_kernel<<<1, 256>>>(nb);
    scan3self_kernel<<<nb, 256>>>();
    scatter_kernel<<<(EE + 255) / 256, 256>>>(src, dst);

    dim3 g1((NN + 127) / 128, 2);
    gemm1_mma_kernel<<<g1, 256>>>(x, as1, ad1);

    int warp_blocks = (NN * 32 + 255) / 256;
    agg1_kernel<<<warp_blocks, 256>>>(b1);

    gemm2_kernel<<<(NN + 63) / 64, 256>>>(W2, as2, ad2);
    agg2_kernel<<<warp_blocks, 256>>>(b2, out);
}

// round 7
// speedup vs baseline: 1.7926x; 1.0385x over previous
#include <cuda_runtime.h>
#include <cuda_fp16.h>
#include <math.h>
#include <cstdint>

#define NN 50000
#define EE 800000
#define ET 850000          // EE + NN self loops
#define FIN 256
#define H1DIM 256          // HEADS*HID
#define HEADS 4
#define HID 64
#define ODIM 32
#define NEG 0.2f

// ---------------- scratch (device globals; no allocs allowed) ----------------
__device__ __half g_h1h[NN * H1DIM];   // x @ W1, fp16 (only consumer: agg1 gather)
__device__ float  g_out1[NN * H1DIM];  // layer1 output (post ELU)
__device__ __half g_h2h[NN * ODIM];    // out1 @ W2, fp16 (only consumer: agg2 gather)
__device__ float  g_W1T[H1DIM * FIN];  // W1 transposed, tf32-rounded: [n][k]
__device__ float  g_as1[NN * HEADS];
__device__ float  g_ad1[NN * HEADS];
__device__ float  g_as2[NN];
__device__ float  g_ad2[NN];
__device__ int    g_rowptr[NN + 1];
__device__ int    g_cnt[NN];
__device__ int    g_col[ET];
__device__ int    g_bsum[256];

typedef unsigned long long ull;

__device__ __forceinline__ uint32_t tf32_rna(float x) {
    uint32_t r;
    asm("cvt.rna.tf32.f32 %0, %1;" : "=r"(r) : "f"(x));
    return r;
}
__device__ __forceinline__ void ffma2(ull& d, ull a, ull b) {
    asm("fma.rn.f32x2 %0, %1, %2, %3;" : "=l"(d) : "l"(a), "l"(b), "l"(d));
}

// ---------------- CSR build ----------------
__global__ void init_w1t_kernel(const float* __restrict__ W1) {
    int b = blockIdx.x;
    if (b < 196) {
        int i = b * 256 + threadIdx.x;
        if (i < NN) g_cnt[i] = 1;   // slot 0 of each row = self loop
    } else {
        int i = (b - 196) * 256 + threadIdx.x;   // n*256+k
        int n = i >> 8, k = i & 255;
        g_W1T[i] = __uint_as_float(tf32_rna(W1[k * 256 + n]));
    }
}

__global__ void count_kernel(const int* __restrict__ dst) {
    int e = blockIdx.x * blockDim.x + threadIdx.x;
    if (e < EE) atomicAdd(&g_cnt[dst[e]], 1);
}

__global__ void scan1_kernel() {
    __shared__ int ws[8];
    int i = blockIdx.x * 256 + threadIdx.x;
    int lane = threadIdx.x & 31, w = threadIdx.x >> 5;
    int v = (i < NN) ? g_cnt[i] : 0;
    int x = v;
    #pragma unroll
    for (int o = 1; o < 32; o <<= 1) {
        int y = __shfl_up_sync(0xffffffffu, x, o);
        if (lane >= o) x += y;
    }
    if (lane == 31) ws[w] = x;
    __syncthreads();
    if (w == 0 && lane < 8) {
        int s = ws[lane];
        #pragma unroll
        for (int o = 1; o < 8; o <<= 1) {
            int y = __shfl_up_sync(0x000000ffu, s, o);
            if (lane >= o) s += y;
        }
        ws[lane] = s;
    }
    __syncthreads();
    int incl = x + (w > 0 ? ws[w - 1] : 0);
    if (i < NN) g_rowptr[i] = incl - v;
    if (threadIdx.x == 255) g_bsum[blockIdx.x] = incl;
}

__global__ void scan2_kernel(int nb) {
    __shared__ int ws[8];
    int t = threadIdx.x, lane = t & 31, w = t >> 5;
    int v = (t < nb) ? g_bsum[t] : 0;
    int x = v;
    #pragma unroll
    for (int o = 1; o < 32; o <<= 1) {
        int y = __shfl_up_sync(0xffffffffu, x, o);
        if (lane >= o) x += y;
    }
    if (lane == 31) ws[w] = x;
    __syncthreads();
    if (w == 0 && lane < 8) {
        int s = ws[lane];
        #pragma unroll
        for (int o = 1; o < 8; o <<= 1) {
            int y = __shfl_up_sync(0x000000ffu, s, o);
            if (lane >= o) s += y;
        }
        ws[lane] = s;
    }
    __syncthreads();
    int incl = x + (w > 0 ? ws[w - 1] : 0);
    if (t < nb) g_bsum[t] = incl - v;
    if (t == nb - 1) g_rowptr[NN] = incl;
}

__global__ void scan3self_kernel() {
    int i = blockIdx.x * 256 + threadIdx.x;
    if (i < NN) {
        int r = g_rowptr[i] + g_bsum[i >> 8];
        g_rowptr[i] = r;
        g_col[r] = i;
        g_cnt[i] = r + 1;
    }
}

__global__ void scatter_kernel(const int* __restrict__ src, const int* __restrict__ dst) {
    int e = blockIdx.x * blockDim.x + threadIdx.x;
    if (e < EE) {
        int d = dst[e];
        int p = atomicAdd(&g_cnt[d], 1);
        g_col[p] = src[e];
    }
}

// ---------------- GEMM1 (mma.sync tf32) + fused alpha1, fp16 h1 output ----------------
#define G1_STRIDE 20

__device__ __forceinline__ void mma_tf32(float* c, const uint32_t* a, const uint32_t* b) {
    asm volatile(
        "mma.sync.aligned.m16n8k8.row.col.f32.tf32.tf32.f32 "
        "{%0,%1,%2,%3}, {%4,%5,%6,%7}, {%8,%9}, {%0,%1,%2,%3};"
        : "+f"(c[0]), "+f"(c[1]), "+f"(c[2]), "+f"(c[3])
        : "r"(a[0]), "r"(a[1]), "r"(a[2]), "r"(a[3]), "r"(b[0]), "r"(b[1]));
}

__global__ void __launch_bounds__(256) gemm1_mma_kernel(const float* __restrict__ x,
                                                        const float* __restrict__ as1,
                                                        const float* __restrict__ ad1) {
    __shared__ float sA[2][128 * G1_STRIDE];
    __shared__ float sB[2][128 * G1_STRIDE];

    int tid  = threadIdx.x;
    int wid  = tid >> 5, lane = tid & 31;
    int qr   = lane >> 2, qc = lane & 3;
    int warpM = (wid & 3) * 32;
    int warpN = (wid >> 2) * 64;
    int row0 = blockIdx.x * 128, col0 = blockIdx.y * 128;

    float c[2][8][4];
    #pragma unroll
    for (int mt = 0; mt < 2; mt++)
        #pragma unroll
        for (int nt = 0; nt < 8; nt++)
            #pragma unroll
            for (int i = 0; i < 4; i++) c[mt][nt][i] = 0.f;

    int lr  = tid >> 2;
    int lk4 = (tid & 3) * 4;

    {
        #pragma unroll
        for (int i = 0; i < 2; i++) {
            int r = lr + i * 64;
            int gr = row0 + r;
            float4 v = make_float4(0.f, 0.f, 0.f, 0.f);
            if (gr < NN) v = *(const float4*)(x + (size_t)gr * 256 + lk4);
            uint4 tv;
            tv.x = tf32_rna(v.x); tv.y = tf32_rna(v.y);
            tv.z = tf32_rna(v.z); tv.w = tf32_rna(v.w);
            *(uint4*)(&sA[0][r * G1_STRIDE + lk4]) = tv;
            float4 wv = *(const float4*)(g_W1T + (size_t)(col0 + r) * 256 + lk4);
            *(float4*)(&sB[0][r * G1_STRIDE + lk4]) = wv;
        }
    }
    __syncthreads();

    #pragma unroll 1
    for (int kt = 0; kt < 16; kt++) {
        int cur = kt & 1;
        float4 av[2], bv[2];
        if (kt < 15) {
            #pragma unroll
            for (int i = 0; i < 2; i++) {
                int r = lr + i * 64;
                int gr = row0 + r;
                av[i] = make_float4(0.f, 0.f, 0.f, 0.f);
                if (gr < NN) av[i] = *(const float4*)(x + (size_t)gr * 256 + (kt + 1) * 16 + lk4);
                bv[i] = *(const float4*)(g_W1T + (size_t)(col0 + r) * 256 + (kt + 1) * 16 + lk4);
            }
        }
        #pragma unroll
        for (int ks = 0; ks < 2; ks++) {
            int kb = ks * 8;
            uint32_t a[2][4], b[8][2];
            #pragma unroll
            for (int mt = 0; mt < 2; mt++) {
                int base = (warpM + mt * 16 + qr) * G1_STRIDE + kb + qc;
                a[mt][0] = __float_as_uint(sA[cur][base]);
                a[mt][1] = __float_as_uint(sA[cur][base + 8 * G1_STRIDE]);
                a[mt][2] = __float_as_uint(sA[cur][base + 4]);
                a[mt][3] = __float_as_uint(sA[cur][base + 8 * G1_STRIDE + 4]);
            }
            #pragma unroll
            for (int nt = 0; nt < 8; nt++) {
                int bb = (warpN + nt * 8 + qr) * G1_STRIDE + kb + qc;
                b[nt][0] = __float_as_uint(sB[cur][bb]);
                b[nt][1] = __float_as_uint(sB[cur][bb + 4]);
            }
            #pragma unroll
            for (int mt = 0; mt < 2; mt++)
                #pragma unroll
                for (int nt = 0; nt < 8; nt++)
                    mma_tf32(c[mt][nt], a[mt], b[nt]);
        }
        if (kt < 15) {
            int nxt = 1 - cur;
            #pragma unroll
            for (int i = 0; i < 2; i++) {
                int r = lr + i * 64;
                uint4 tv;
                tv.x = tf32_rna(av[i].x); tv.y = tf32_rna(av[i].y);
                tv.z = tf32_rna(av[i].z); tv.w = tf32_rna(av[i].w);
                *(uint4*)(&sA[nxt][r * G1_STRIDE + lk4]) = tv;
                *(float4*)(&sB[nxt][r * G1_STRIDE + lk4]) = bv[i];
            }
            __syncthreads();
        }
    }

    // epilogue: store h1 as fp16
    #pragma unroll
    for (int mt = 0; mt < 2; mt++) {
        int r1 = row0 + warpM + mt * 16 + qr;
        int r2 = r1 + 8;
        #pragma unroll
        for (int nt = 0; nt < 8; nt++) {
            int cc = col0 + warpN + nt * 8 + qc * 2;
            if (r1 < NN)
                *(__half2*)(g_h1h + (size_t)r1 * 256 + cc) = __floats2half2_rn(c[mt][nt][0], c[mt][nt][1]);
            if (r2 < NN)
                *(__half2*)(g_h1h + (size_t)r2 * 256 + cc) = __floats2half2_rn(c[mt][nt][2], c[mt][nt][3]);
        }
    }

    // fused alpha1 (fp32 fragments, exact)
    int h = blockIdx.y * 2 + (wid >> 2);
    float asv[16], adv[16];
    #pragma unroll
    for (int nt = 0; nt < 8; nt++)
        #pragma unroll
        for (int i = 0; i < 2; i++) {
            int cl = nt * 8 + qc * 2 + i;
            asv[nt * 2 + i] = as1[h * 64 + cl];
            adv[nt * 2 + i] = ad1[h * 64 + cl];
        }
    #pragma unroll
    for (int mt = 0; mt < 2; mt++) {
        float ps1 = 0.f, pd1 = 0.f, ps2 = 0.f, pd2 = 0.f;
        #pragma unroll
        for (int nt = 0; nt < 8; nt++) {
            ps1 += c[mt][nt][0] * asv[nt * 2] + c[mt][nt][1] * asv[nt * 2 + 1];
            pd1 += c[mt][nt][0] * adv[nt * 2] + c[mt][nt][1] * adv[nt * 2 + 1];
            ps2 += c[mt][nt][2] * asv[nt * 2] + c[mt][nt][3] * asv[nt * 2 + 1];
            pd2 += c[mt][nt][2] * adv[nt * 2] + c[mt][nt][3] * adv[nt * 2 + 1];
        }
        #pragma unroll
        for (int o = 1; o <= 2; o <<= 1) {
            ps1 += __shfl_xor_sync(0xffffffffu, ps1, o);
            pd1 += __shfl_xor_sync(0xffffffffu, pd1, o);
            ps2 += __shfl_xor_sync(0xffffffffu, ps2, o);
            pd2 += __shfl_xor_sync(0xffffffffu, pd2, o);
        }
        if (qc == 0) {
            int r1 = row0 + warpM + mt * 16 + qr, r2 = r1 + 8;
            if (r1 < NN) { g_as1[r1 * 4 + h] = ps1; g_ad1[r1 * 4 + h] = pd1; }
            if (r2 < NN) { g_as1[r2 * 4 + h] = ps2; g_ad1[r2 * 4 + h] = pd2; }
        }
    }
}

__device__ __forceinline__ float lrelu(float e) { return e >= 0.f ? e : NEG * e; }

// ---------------- layer1 softmax (no-max) + aggregate + bias + ELU ----------------
__global__ void agg1_kernel(const float* __restrict__ b1) {
    int n    = (blockIdx.x * blockDim.x + threadIdx.x) >> 5;
    int lane = threadIdx.x & 31;
    if (n >= NN) return;
    int beg = g_rowptr[n], end = g_rowptr[n + 1];
    float4 ad = *(const float4*)(g_ad1 + n * 4);

    // pass 1: denom
    float4 dn = make_float4(0.f, 0.f, 0.f, 0.f);
    for (int j = beg + lane; j < end; j += 32) {
        int s = g_col[j];
        float4 as = *(const float4*)(g_as1 + s * 4);
        dn.x += __expf(lrelu(as.x + ad.x));
        dn.y += __expf(lrelu(as.y + ad.y));
        dn.z += __expf(lrelu(as.z + ad.z));
        dn.w += __expf(lrelu(as.w + ad.w));
    }
    #pragma unroll
    for (int o = 16; o; o >>= 1) {
        dn.x += __shfl_xor_sync(0xffffffffu, dn.x, o);
        dn.y += __shfl_xor_sync(0xffffffffu, dn.y, o);
        dn.z += __shfl_xor_sync(0xffffffffu, dn.z, o);
        dn.w += __shfl_xor_sync(0xffffffffu, dn.w, o);
    }
    int h = lane >> 3;
    float dh = (h == 0) ? dn.x : (h == 1) ? dn.y : (h == 2) ? dn.z : dn.w;
    float ah = (h == 0) ? ad.x : (h == 1) ? ad.y : (h == 2) ? ad.z : ad.w;
    float ih = 1.0f / (dh + 1e-16f);

    float acc[8];
    #pragma unroll
    for (int i = 0; i < 8; i++) acc[i] = 0.f;

    // pass 2: weighted accumulation (fp16 gather, fp32 accumulate)
    for (int j = beg; j < end; j++) {
        int s = g_col[j];
        float asv = g_as1[s * 4 + h];
        float alpha = __expf(lrelu(asv + ah)) * ih;
        __half2 hh[4];
        *(uint4*)hh = *(const uint4*)(g_h1h + (size_t)s * 256 + lane * 8);
        float2 f0 = __half22float2(hh[0]);
        float2 f1 = __half22float2(hh[1]);
        float2 f2 = __half22float2(hh[2]);
        float2 f3 = __half22float2(hh[3]);
        acc[0] += alpha * f0.x; acc[1] += alpha * f0.y;
        acc[2] += alpha * f1.x; acc[3] += alpha * f1.y;
        acc[4] += alpha * f2.x; acc[5] += alpha * f2.y;
        acc[6] += alpha * f3.x; acc[7] += alpha * f3.y;
    }
    float4 bb1 = *(const float4*)(b1 + lane * 8);
    float4 bb2 = *(const float4*)(b1 + lane * 8 + 4);
    float o0 = acc[0] + bb1.x, o1 = acc[1] + bb1.y, o2 = acc[2] + bb1.z, o3 = acc[3] + bb1.w;
    float o4 = acc[4] + bb2.x, o5 = acc[5] + bb2.y, o6 = acc[6] + bb2.z, o7 = acc[7] + bb2.w;
    o0 = o0 > 0.f ? o0 : expm1f(o0);  o1 = o1 > 0.f ? o1 : expm1f(o1);
    o2 = o2 > 0.f ? o2 : expm1f(o2);  o3 = o3 > 0.f ? o3 : expm1f(o3);
    o4 = o4 > 0.f ? o4 : expm1f(o4);  o5 = o5 > 0.f ? o5 : expm1f(o5);
    o6 = o6 > 0.f ? o6 : expm1f(o6);  o7 = o7 > 0.f ? o7 : expm1f(o7);
    float* op = g_out1 + (size_t)n * 256 + lane * 8;
    *(float4*)(op)     = make_float4(o0, o1, o2, o3);
    *(float4*)(op + 4) = make_float4(o4, o5, o6, o7);
}

// ---------------- GEMM2 (f32x2) + fused alpha2, fp16 h2 output ----------------
#define W2S 258
__global__ void gemm2_kernel(const float* __restrict__ B,
                             const float* __restrict__ asrc,
                             const float* __restrict__ adst) {
    __shared__ float sW[32 * W2S];    // W2 transposed: sW[c][k]
    __shared__ float sA[64][32];
    int t = threadIdx.x;
    for (int i = t; i < 8192; i += 256) {
        int c = i & 31, k = i >> 5;
        sW[c * W2S + k] = B[k * 32 + c];
    }
    __syncthreads();

    int row0 = blockIdx.x * 64;
    int lane = t & 31;
    int rg = t >> 5;
    float a2s = asrc[lane], a2d = adst[lane];
    ull acc2[8];
    #pragma unroll
    for (int i = 0; i < 8; i++) acc2[i] = 0ULL;

    for (int k0 = 0; k0 < 256; k0 += 32) {
        __syncthreads();
        #pragma unroll
        for (int i = 0; i < 2; i++) {
            int idx = t + i * 256;
            int r  = idx >> 3;
            int k4 = (idx & 7) * 4;
            int gr = row0 + r;
            float4 v = make_float4(0.f, 0.f, 0.f, 0.f);
            if (gr < NN) v = *(const float4*)(g_out1 + (size_t)gr * 256 + k0 + k4);
            *(float4*)(&sA[r][k4]) = v;
        }
        __syncthreads();
        #pragma unroll
        for (int kk = 0; kk < 32; kk += 2) {
            ull b2 = *(const ull*)(&sW[lane * W2S + k0 + kk]);
            #pragma unroll
            for (int i = 0; i < 8; i++) {
                ull a2 = *(const ull*)(&sA[rg * 8 + i][kk]);
                ffma2(acc2[i], a2, b2);
            }
        }
    }
    #pragma unroll
    for (int i = 0; i < 8; i++) {
        int r = row0 + rg * 8 + i;
        float2 p = *(float2*)(&acc2[i]);
        float v = p.x + p.y;
        if (r < NN) g_h2h[r * 32 + lane] = __float2half_rn(v);
        float ps = v * a2s, pd = v * a2d;
        #pragma unroll
        for (int o = 16; o; o >>= 1) {
            ps += __shfl_xor_sync(0xffffffffu, ps, o);
            pd += __shfl_xor_sync(0xffffffffu, pd, o);
        }
        if (lane == 0 && r < NN) { g_as2[r] = ps; g_ad2[r] = pd; }
    }
}

// ---------------- layer2 softmax (no-max) + aggregate + bias ----------------
__global__ void agg2_kernel(const float* __restrict__ b2, float* __restrict__ out) {
    int n    = (blockIdx.x * blockDim.x + threadIdx.x) >> 5;
    int lane = threadIdx.x & 31;
    if (n >= NN) return;
    int beg = g_rowptr[n], end = g_rowptr[n + 1];
    float ad = g_ad2[n];

    float dn = 0.f;
    for (int j = beg + lane; j < end; j += 32)
        dn += __expf(lrelu(g_as2[g_col[j]] + ad));
    #pragma unroll
    for (int o = 16; o; o >>= 1) dn += __shfl_xor_sync(0xffffffffu, dn, o);
    float ih = 1.0f / (dn + 1e-16f);

    float acc = 0.f;
    for (int j = beg; j < end; j++) {
        int s = g_col[j];
        float alpha = __expf(lrelu(g_as2[s] + ad)) * ih;
        acc += alpha * __half2float(g_h2h[s * 32 + lane]);
    }
    out[n * 32 + lane] = acc + b2[lane];
}

// ---------------- launch ----------------
extern "C" void kernel_launch(void* const* d_in, const int* in_sizes, int n_in,
                              void* d_out, int out_size) {
    const float* x   = (const float*)d_in[0];
    const int*   ei  = (const int*)  d_in[1];
    const float* W1  = (const float*)d_in[2];
    const float* as1 = (const float*)d_in[3];
    const float* ad1 = (const float*)d_in[4];
    const float* b1  = (const float*)d_in[5];
    const float* W2  = (const float*)d_in[6];
    const float* as2 = (const float*)d_in[7];
    const float* ad2 = (const float*)d_in[8];
    const float* b2  = (const float*)d_in[9];
    float* out = (float*)d_out;

    const int* src = ei;
    const int* dst = ei + EE;

    int nb = (NN + 255) / 256;   // 196

    init_w1t_kernel<<<nb + 256, 256>>>(W1);
    count_kernel<<<(EE + 255) / 256, 256>>>(dst);
    scan1_kernel<<<nb, 256>>>();
    scan2_kernel<<<1, 256>>>(nb);
    scan3self_kernel<<<nb, 256>>>();
    scatter_kernel<<<(EE + 255) / 256, 256>>>(src, dst);

    dim3 g1((NN + 127) / 128, 2);
    gemm1_mma_kernel<<<g1, 256>>>(x, as1, ad1);

    int warp_blocks = (NN * 32 + 255) / 256;
    agg1_kernel<<<warp_blocks, 256>>>(b1);

    gemm2_kernel<<<(NN + 63) / 64, 256>>>(W2, as2, ad2);
    agg2_kernel<<<warp_blocks, 256>>>(b2, out);
}

// round 9
// speedup vs baseline: 2.0486x; 1.1428x over previous
#include <cuda_runtime.h>
#include <cuda_fp16.h>
#include <math.h>
#include <cstdint>

#define NN 50000
#define EE 800000
#define ET 850000          // EE + NN self loops
#define FIN 256
#define H1DIM 256          // HEADS*HID
#define HEADS 4
#define HID 64
#define ODIM 32
#define NEG 0.2f

// ---------------- scratch (device globals; no allocs allowed) ----------------
__device__ __half g_h1h[NN * H1DIM];   // x @ W1, fp16 (consumer: agg1 gather)
__device__ __half g_out1h[NN * H1DIM]; // layer1 output post ELU, fp16 (consumer: gemm2)
__device__ __half g_h2h[NN * ODIM];    // out1 @ W2, fp16 (consumer: agg2 gather)
__device__ float  g_W1T[H1DIM * FIN];  // W1 transposed, tf32-rounded: [n][k]
__device__ float  g_as1[NN * HEADS];
__device__ float  g_ad1[NN * HEADS];
__device__ float  g_as2[NN];
__device__ float  g_ad2[NN];
__device__ int    g_rowptr[NN + 1];
__device__ int    g_cnt[NN];
__device__ int    g_col[ET];
__device__ int    g_bsum[256];

typedef unsigned long long ull;

__device__ __forceinline__ uint32_t tf32_rna(float x) {
    uint32_t r;
    asm("cvt.rna.tf32.f32 %0, %1;" : "=r"(r) : "f"(x));
    return r;
}
__device__ __forceinline__ void ffma2(ull& d, ull a, ull b) {
    asm("fma.rn.f32x2 %0, %1, %2, %3;" : "=l"(d) : "l"(a), "l"(b), "l"(d));
}

// ---------------- CSR build ----------------
__global__ void init_cnt_kernel() {
    int i = blockIdx.x * 256 + threadIdx.x;
    if (i < NN) g_cnt[i] = 1;   // slot 0 of each row = self loop
}

__global__ void w1t_kernel(const float* __restrict__ W1) {
    int i = blockIdx.x * 256 + threadIdx.x;   // n*256+k
    int n = i >> 8, k = i & 255;
    g_W1T[i] = __uint_as_float(tf32_rna(W1[k * 256 + n]));
}

__global__ void count_kernel(const int* __restrict__ dst) {
    int e = blockIdx.x * blockDim.x + threadIdx.x;
    if (e < EE) atomicAdd(&g_cnt[dst[e]], 1);
}

__global__ void scan1_kernel() {
    __shared__ int ws[8];
    int i = blockIdx.x * 256 + threadIdx.x;
    int lane = threadIdx.x & 31, w = threadIdx.x >> 5;
    int v = (i < NN) ? g_cnt[i] : 0;
    int x = v;
    #pragma unroll
    for (int o = 1; o < 32; o <<= 1) {
        int y = __shfl_up_sync(0xffffffffu, x, o);
        if (lane >= o) x += y;
    }
    if (lane == 31) ws[w] = x;
    __syncthreads();
    if (w == 0 && lane < 8) {
        int s = ws[lane];
        #pragma unroll
        for (int o = 1; o < 8; o <<= 1) {
            int y = __shfl_up_sync(0x000000ffu, s, o);
            if (lane >= o) s += y;
        }
        ws[lane] = s;
    }
    __syncthreads();
    int incl = x + (w > 0 ? ws[w - 1] : 0);
    if (i < NN) g_rowptr[i] = incl - v;
    if (threadIdx.x == 255) g_bsum[blockIdx.x] = incl;
}

__global__ void scan2_kernel(int nb) {
    __shared__ int ws[8];
    int t = threadIdx.x, lane = t & 31, w = t >> 5;
    int v = (t < nb) ? g_bsum[t] : 0;
    int x = v;
    #pragma unroll
    for (int o = 1; o < 32; o <<= 1) {
        int y = __shfl_up_sync(0xffffffffu, x, o);
        if (lane >= o) x += y;
    }
    if (lane == 31) ws[w] = x;
    __syncthreads();
    if (w == 0 && lane < 8) {
        int s = ws[lane];
        #pragma unroll
        for (int o = 1; o < 8; o <<= 1) {
            int y = __shfl_up_sync(0x000000ffu, s, o);
            if (lane >= o) s += y;
        }
        ws[lane] = s;
    }
    __syncthreads();
    int incl = x + (w > 0 ? ws[w - 1] : 0);
    if (t < nb) g_bsum[t] = incl - v;
    if (t == nb - 1) g_rowptr[NN] = incl;
}

__global__ void scan3self_kernel() {
    int i = blockIdx.x * 256 + threadIdx.x;
    if (i < NN) {
        int r = g_rowptr[i] + g_bsum[i >> 8];
        g_rowptr[i] = r;
        g_col[r] = i;
        g_cnt[i] = r + 1;
    }
}

__global__ void scatter_kernel(const int* __restrict__ src, const int* __restrict__ dst) {
    int e = blockIdx.x * blockDim.x + threadIdx.x;
    if (e < EE) {
        int d = dst[e];
        int p = atomicAdd(&g_cnt[d], 1);
        g_col[p] = src[e];
    }
}

// ---------------- GEMM1 (mma.sync tf32) + fused alpha1, fp16 h1 output ----------------
#define G1_STRIDE 20

__device__ __forceinline__ void mma_tf32(float* c, const uint32_t* a, const uint32_t* b) {
    asm volatile(
        "mma.sync.aligned.m16n8k8.row.col.f32.tf32.tf32.f32 "
        "{%0,%1,%2,%3}, {%4,%5,%6,%7}, {%8,%9}, {%0,%1,%2,%3};"
        : "+f"(c[0]), "+f"(c[1]), "+f"(c[2]), "+f"(c[3])
        : "r"(a[0]), "r"(a[1]), "r"(a[2]), "r"(a[3]), "r"(b[0]), "r"(b[1]));
}

__global__ void __launch_bounds__(256) gemm1_mma_kernel(const float* __restrict__ x,
                                                        const float* __restrict__ as1,
                                                        const float* __restrict__ ad1) {
    __shared__ float sA[2][128 * G1_STRIDE];
    __shared__ float sB[2][128 * G1_STRIDE];

    int tid  = threadIdx.x;
    int wid  = tid >> 5, lane = tid & 31;
    int qr   = lane >> 2, qc = lane & 3;
    int warpM = (wid & 3) * 32;
    int warpN = (wid >> 2) * 64;
    int row0 = blockIdx.x * 128, col0 = blockIdx.y * 128;

    float c[2][8][4];
    #pragma unroll
    for (int mt = 0; mt < 2; mt++)
        #pragma unroll
        for (int nt = 0; nt < 8; nt++)
            #pragma unroll
            for (int i = 0; i < 4; i++) c[mt][nt][i] = 0.f;

    int lr  = tid >> 2;
    int lk4 = (tid & 3) * 4;

    {
        #pragma unroll
        for (int i = 0; i < 2; i++) {
            int r = lr + i * 64;
            int gr = row0 + r;
            float4 v = make_float4(0.f, 0.f, 0.f, 0.f);
            if (gr < NN) v = *(const float4*)(x + (size_t)gr * 256 + lk4);
            uint4 tv;
            tv.x = tf32_rna(v.x); tv.y = tf32_rna(v.y);
            tv.z = tf32_rna(v.z); tv.w = tf32_rna(v.w);
            *(uint4*)(&sA[0][r * G1_STRIDE + lk4]) = tv;
            float4 wv = *(const float4*)(g_W1T + (size_t)(col0 + r) * 256 + lk4);
            *(float4*)(&sB[0][r * G1_STRIDE + lk4]) = wv;
        }
    }
    __syncthreads();

    #pragma unroll 1
    for (int kt = 0; kt < 16; kt++) {
        int cur = kt & 1;
        float4 av[2], bv[2];
        if (kt < 15) {
            #pragma unroll
            for (int i = 0; i < 2; i++) {
                int r = lr + i * 64;
                int gr = row0 + r;
                av[i] = make_float4(0.f, 0.f, 0.f, 0.f);
                if (gr < NN) av[i] = *(const float4*)(x + (size_t)gr * 256 + (kt + 1) * 16 + lk4);
                bv[i] = *(const float4*)(g_W1T + (size_t)(col0 + r) * 256 + (kt + 1) * 16 + lk4);
            }
        }
        #pragma unroll
        for (int ks = 0; ks < 2; ks++) {
            int kb = ks * 8;
            uint32_t a[2][4], b[8][2];
            #pragma unroll
            for (int mt = 0; mt < 2; mt++) {
                int base = (warpM + mt * 16 + qr) * G1_STRIDE + kb + qc;
                a[mt][0] = __float_as_uint(sA[cur][base]);
                a[mt][1] = __float_as_uint(sA[cur][base + 8 * G1_STRIDE]);
                a[mt][2] = __float_as_uint(sA[cur][base + 4]);
                a[mt][3] = __float_as_uint(sA[cur][base + 8 * G1_STRIDE + 4]);
            }
            #pragma unroll
            for (int nt = 0; nt < 8; nt++) {
                int bb = (warpN + nt * 8 + qr) * G1_STRIDE + kb + qc;
                b[nt][0] = __float_as_uint(sB[cur][bb]);
                b[nt][1] = __float_as_uint(sB[cur][bb + 4]);
            }
            #pragma unroll
            for (int mt = 0; mt < 2; mt++)
                #pragma unroll
                for (int nt = 0; nt < 8; nt++)
                    mma_tf32(c[mt][nt], a[mt], b[nt]);
        }
        if (kt < 15) {
            int nxt = 1 - cur;
            #pragma unroll
            for (int i = 0; i < 2; i++) {
                int r = lr + i * 64;
                uint4 tv;
                tv.x = tf32_rna(av[i].x); tv.y = tf32_rna(av[i].y);
                tv.z = tf32_rna(av[i].z); tv.w = tf32_rna(av[i].w);
                *(uint4*)(&sA[nxt][r * G1_STRIDE + lk4]) = tv;
                *(float4*)(&sB[nxt][r * G1_STRIDE + lk4]) = bv[i];
            }
            __syncthreads();
        }
    }

    // epilogue: store h1 as fp16
    #pragma unroll
    for (int mt = 0; mt < 2; mt++) {
        int r1 = row0 + warpM + mt * 16 + qr;
        int r2 = r1 + 8;
        #pragma unroll
        for (int nt = 0; nt < 8; nt++) {
            int cc = col0 + warpN + nt * 8 + qc * 2;
            if (r1 < NN)
                *(__half2*)(g_h1h + (size_t)r1 * 256 + cc) = __floats2half2_rn(c[mt][nt][0], c[mt][nt][1]);
            if (r2 < NN)
                *(__half2*)(g_h1h + (size_t)r2 * 256 + cc) = __floats2half2_rn(c[mt][nt][2], c[mt][nt][3]);
        }
    }

    // fused alpha1 (fp32 fragments, exact)
    int h = blockIdx.y * 2 + (wid >> 2);
    float asv[16], adv[16];
    #pragma unroll
    for (int nt = 0; nt < 8; nt++)
        #pragma unroll
        for (int i = 0; i < 2; i++) {
            int cl = nt * 8 + qc * 2 + i;
            asv[nt * 2 + i] = as1[h * 64 + cl];
            adv[nt * 2 + i] = ad1[h * 64 + cl];
        }
    #pragma unroll
    for (int mt = 0; mt < 2; mt++) {
        float ps1 = 0.f, pd1 = 0.f, ps2 = 0.f, pd2 = 0.f;
        #pragma unroll
        for (int nt = 0; nt < 8; nt++) {
            ps1 += c[mt][nt][0] * asv[nt * 2] + c[mt][nt][1] * asv[nt * 2 + 1];
            pd1 += c[mt][nt][0] * adv[nt * 2] + c[mt][nt][1] * adv[nt * 2 + 1];
            ps2 += c[mt][nt][2] * asv[nt * 2] + c[mt][nt][3] * asv[nt * 2 + 1];
            pd2 += c[mt][nt][2] * adv[nt * 2] + c[mt][nt][3] * adv[nt * 2 + 1];
        }
        #pragma unroll
        for (int o = 1; o <= 2; o <<= 1) {
            ps1 += __shfl_xor_sync(0xffffffffu, ps1, o);
            pd1 += __shfl_xor_sync(0xffffffffu, pd1, o);
            ps2 += __shfl_xor_sync(0xffffffffu, ps2, o);
            pd2 += __shfl_xor_sync(0xffffffffu, pd2, o);
        }
        if (qc == 0) {
            int r1 = row0 + warpM + mt * 16 + qr, r2 = r1 + 8;
            if (r1 < NN) { g_as1[r1 * 4 + h] = ps1; g_ad1[r1 * 4 + h] = pd1; }
            if (r2 < NN) { g_as1[r2 * 4 + h] = ps2; g_ad1[r2 * 4 + h] = pd2; }
        }
    }
}

__device__ __forceinline__ float lrelu(float e) { return e >= 0.f ? e : NEG * e; }

// ---------------- layer1: single-pass softmax + aggregate + bias + ELU ----------------
// out = (sum_j w_j h_j) / (sum_j w_j + 1e-16), w_j = exp(lrelu(as[src]+ad[dst]))
__global__ void agg1_kernel(const float* __restrict__ b1) {
    int n    = (blockIdx.x * blockDim.x + threadIdx.x) >> 5;
    int lane = threadIdx.x & 31;
    if (n >= NN) return;
    int beg = g_rowptr[n], end = g_rowptr[n + 1];
    int h = lane >> 3;
    float ah = g_ad1[n * 4 + h];

    float dn = 0.f;
    float acc[8];
    #pragma unroll
    for (int i = 0; i < 8; i++) acc[i] = 0.f;

    int j = beg;
    for (; j + 2 <= end; j += 2) {
        int s0 = g_col[j], s1 = g_col[j + 1];
        float w0 = __expf(lrelu(g_as1[s0 * 4 + h] + ah));
        float w1 = __expf(lrelu(g_as1[s1 * 4 + h] + ah));
        uint4 p0 = *(const uint4*)(g_h1h + (size_t)s0 * 256 + lane * 8);
        uint4 p1 = *(const uint4*)(g_h1h + (size_t)s1 * 256 + lane * 8);
        dn += w0 + w1;
        __half2* q0 = (__half2*)&p0;
        __half2* q1 = (__half2*)&p1;
        #pragma unroll
        for (int i = 0; i < 4; i++) {
            float2 f0 = __half22float2(q0[i]);
            float2 f1 = __half22float2(q1[i]);
            acc[2 * i]     += w0 * f0.x + w1 * f1.x;
            acc[2 * i + 1] += w0 * f0.y + w1 * f1.y;
        }
    }
    if (j < end) {
        int s0 = g_col[j];
        float w0 = __expf(lrelu(g_as1[s0 * 4 + h] + ah));
        uint4 p0 = *(const uint4*)(g_h1h + (size_t)s0 * 256 + lane * 8);
        dn += w0;
        __half2* q0 = (__half2*)&p0;
        #pragma unroll
        for (int i = 0; i < 4; i++) {
            float2 f0 = __half22float2(q0[i]);
            acc[2 * i]     += w0 * f0.x;
            acc[2 * i + 1] += w0 * f0.y;
        }
    }
    float ih = 1.0f / (dn + 1e-16f);
    float4 bb1 = *(const float4*)(b1 + lane * 8);
    float4 bb2 = *(const float4*)(b1 + lane * 8 + 4);
    float o0 = acc[0] * ih + bb1.x, o1 = acc[1] * ih + bb1.y;
    float o2 = acc[2] * ih + bb1.z, o3 = acc[3] * ih + bb1.w;
    float o4 = acc[4] * ih + bb2.x, o5 = acc[5] * ih + bb2.y;
    float o6 = acc[6] * ih + bb2.z, o7 = acc[7] * ih + bb2.w;
    o0 = o0 > 0.f ? o0 : expm1f(o0);  o1 = o1 > 0.f ? o1 : expm1f(o1);
    o2 = o2 > 0.f ? o2 : expm1f(o2);  o3 = o3 > 0.f ? o3 : expm1f(o3);
    o4 = o4 > 0.f ? o4 : expm1f(o4);  o5 = o5 > 0.f ? o5 : expm1f(o5);
    o6 = o6 > 0.f ? o6 : expm1f(o6);  o7 = o7 > 0.f ? o7 : expm1f(o7);
    uint4 pk;
    __half2* ph = (__half2*)&pk;
    ph[0] = __floats2half2_rn(o0, o1);
    ph[1] = __floats2half2_rn(o2, o3);
    ph[2] = __floats2half2_rn(o4, o5);
    ph[3] = __floats2half2_rn(o6, o7);
    *(uint4*)(g_out1h + (size_t)n * 256 + lane * 8) = pk;
}

// ---------------- GEMM2 (f32x2, fp16 input) + fused alpha2, fp16 h2 output ----------------
#define W2S 258
__global__ void gemm2_kernel(const float* __restrict__ B,
                             const float* __restrict__ asrc,
                             const float* __restrict__ adst) {
    __shared__ float sW[32 * W2S];    // W2 transposed: sW[c][k]
    __shared__ float sA[64][32];
    int t = threadIdx.x;
    for (int i = t; i < 8192; i += 256) {
        int c = i & 31, k = i >> 5;
        sW[c * W2S + k] = B[k * 32 + c];
    }
    __syncthreads();

    int row0 = blockIdx.x * 64;
    int lane = t & 31;
    int rg = t >> 5;
    float a2s = asrc[lane], a2d = adst[lane];
    ull acc2[8];
    #pragma unroll
    for (int i = 0; i < 8; i++) acc2[i] = 0ULL;

    int lrr = t >> 2;          // 0..63 (row)
    int lk8 = (t & 3) * 8;     // 0,8,16,24

    for (int k0 = 0; k0 < 256; k0 += 32) {
        __syncthreads();
        {
            int gr = row0 + lrr;
            uint4 v = make_uint4(0u, 0u, 0u, 0u);
            if (gr < NN) v = *(const uint4*)(g_out1h + (size_t)gr * 256 + k0 + lk8);
            __half2* q = (__half2*)&v;
            #pragma unroll
            for (int i = 0; i < 4; i++) {
                float2 f = __half22float2(q[i]);
                sA[lrr][lk8 + 2 * i]     = f.x;
                sA[lrr][lk8 + 2 * i + 1] = f.y;
            }
        }
        __syncthreads();
        #pragma unroll
        for (int kk = 0; kk < 32; kk += 2) {
            ull b2 = *(const ull*)(&sW[lane * W2S + k0 + kk]);
            #pragma unroll
            for (int i = 0; i < 8; i++) {
                ull a2 = *(const ull*)(&sA[rg * 8 + i][kk]);
                ffma2(acc2[i], a2, b2);
            }
        }
    }
    #pragma unroll
    for (int i = 0; i < 8; i++) {
        int r = row0 + rg * 8 + i;
        float2 p = *(float2*)(&acc2[i]);
        float v = p.x + p.y;
        if (r < NN) g_h2h[r * 32 + lane] = __float2half_rn(v);
        float ps = v * a2s, pd = v * a2d;
        #pragma unroll
        for (int o = 16; o; o >>= 1) {
            ps += __shfl_xor_sync(0xffffffffu, ps, o);
            pd += __shfl_xor_sync(0xffffffffu, pd, o);
        }
        if (lane == 0 && r < NN) { g_as2[r] = ps; g_ad2[r] = pd; }
    }
}

// ---------------- layer2: single-pass softmax + aggregate + bias ----------------
__global__ void agg2_kernel(const float* __restrict__ b2, float* __restrict__ out) {
    int n    = (blockIdx.x * blockDim.x + threadIdx.x) >> 5;
    int lane = threadIdx.x & 31;
    if (n >= NN) return;
    int beg = g_rowptr[n], end = g_rowptr[n + 1];
    float ad = g_ad2[n];

    float dn = 0.f, acc = 0.f;
    int j = beg;
    for (; j + 2 <= end; j += 2) {
        int s0 = g_col[j], s1 = g_col[j + 1];
        float w0 = __expf(lrelu(g_as2[s0] + ad));
        float w1 = __expf(lrelu(g_as2[s1] + ad));
        float v0 = __half2float(g_h2h[s0 * 32 + lane]);
        float v1 = __half2float(g_h2h[s1 * 32 + lane]);
        dn += w0 + w1;
        acc += w0 * v0 + w1 * v1;
    }
    if (j < end) {
        int s0 = g_col[j];
        float w0 = __expf(lrelu(g_as2[s0] + ad));
        dn += w0;
        acc += w0 * __half2float(g_h2h[s0 * 32 + lane]);
    }
    out[n * 32 + lane] = acc / (dn + 1e-16f) + b2[lane];
}

// ---------------- launch ----------------
extern "C" void kernel_launch(void* const* d_in, const int* in_sizes, int n_in,
                              void* d_out, int out_size) {
    const float* x   = (const float*)d_in[0];
    const int*   ei  = (const int*)  d_in[1];
    const float* W1  = (const float*)d_in[2];
    const float* as1 = (const float*)d_in[3];
    const float* ad1 = (const float*)d_in[4];
    const float* b1  = (const float*)d_in[5];
    const float* W2  = (const float*)d_in[6];
    const float* as2 = (const float*)d_in[7];
    const float* ad2 = (const float*)d_in[8];
    const float* b2  = (const float*)d_in[9];
    float* out = (float*)d_out;

    const int* src = ei;
    const int* dst = ei + EE;

    int nb = (NN + 255) / 256;   // 196

    // fork a worker stream: gemm1 path runs concurrently with the CSR build
    cudaStream_t sB;
    cudaStreamCreate(&sB);
    cudaEvent_t evF, evJ;
    cudaEventCreateWithFlags(&evF, cudaEventDisableTiming);
    cudaEventCreateWithFlags(&evJ, cudaEventDisableTiming);

    cudaEventRecord(evF, 0);
    cudaStreamWaitEvent(sB, evF, 0);
    w1t_kernel<<<256, 256, 0, sB>>>(W1);
    dim3 g1((NN + 127) / 128, 2);
    gemm1_mma_kernel<<<g1, 256, 0, sB>>>(x, as1, ad1);
    cudaEventRecord(evJ, sB);

    // CSR build on the origin stream (overlaps with gemm1)
    init_cnt_kernel<<<nb, 256>>>();
    count_kernel<<<(EE + 255) / 256, 256>>>(dst);
    scan1_kernel<<<nb, 256>>>();
    scan2_kernel<<<1, 256>>>(nb);
    scan3self_kernel<<<nb, 256>>>();
    scatter_kernel<<<(EE + 255) / 256, 256>>>(src, dst);

    // join: agg1 needs CSR + gemm1
    cudaStreamWaitEvent(0, evJ, 0);

    int warp_blocks = (NN * 32 + 255) / 256;
    agg1_kernel<<<warp_blocks, 256>>>(b1);
    gemm2_kernel<<<(NN + 63) / 64, 256>>>(W2, as2, ad2);
    agg2_kernel<<<warp_blocks, 256>>>(b2, out);
    // note: sB/evF/evJ intentionally not destroyed here — they may be
    // referenced by an in-progress stream capture; handles are tiny.
}

// round 10
// speedup vs baseline: 2.0505x; 1.0009x over previous
#include <cuda_runtime.h>
#include <cuda_fp16.h>
#include <math.h>
#include <cstdint>

#define NN 50000
#define EE 800000
#define ET 850000          // EE + NN self loops
#define FIN 256
#define H1DIM 256          // HEADS*HID
#define HEADS 4
#define HID 64
#define ODIM 32
#define NEG 0.2f

// ---------------- scratch (device globals; no allocs allowed) ----------------
__device__ __half g_h1h[NN * H1DIM];   // x @ W1, fp16 (consumer: agg1 gather)
__device__ __half g_out1h[NN * H1DIM]; // layer1 output post ELU, fp16 (consumer: gemm2)
__device__ __half g_h2h[NN * ODIM];    // out1 @ W2, fp16 (consumer: agg2 gather)
__device__ float  g_W1T[H1DIM * FIN];  // W1 transposed, tf32-rounded: [n][k]
__device__ float  g_as1[NN * HEADS];
__device__ float  g_ad1[NN * HEADS];
__device__ float  g_as2[NN];
__device__ float  g_ad2[NN];
__device__ int    g_rowptr[NN + 1];
__device__ int    g_cnt[NN];
__device__ int    g_col[ET];
__device__ int    g_dstA[ET];          // dst node per CSR slot
__device__ float  g_w1[ET * 4];        // per-slot layer1 weights (4 heads)
__device__ float  g_w2[ET];            // per-slot layer2 weights
__device__ int    g_bsum[256];

typedef unsigned long long ull;

__device__ __forceinline__ uint32_t tf32_rna(float x) {
    uint32_t r;
    asm("cvt.rna.tf32.f32 %0, %1;" : "=r"(r) : "f"(x));
    return r;
}
__device__ __forceinline__ void ffma2(ull& d, ull a, ull b) {
    asm("fma.rn.f32x2 %0, %1, %2, %3;" : "=l"(d) : "l"(a), "l"(b), "l"(d));
}
__device__ __forceinline__ float lrelu(float e) { return e >= 0.f ? e : NEG * e; }

// ---------------- CSR build ----------------
__global__ void init_cnt_kernel() {
    int i = blockIdx.x * 256 + threadIdx.x;
    if (i < NN) g_cnt[i] = 1;   // slot 0 of each row = self loop
}

__global__ void w1t_kernel(const float* __restrict__ W1) {
    int i = blockIdx.x * 256 + threadIdx.x;   // n*256+k
    int n = i >> 8, k = i & 255;
    g_W1T[i] = __uint_as_float(tf32_rna(W1[k * 256 + n]));
}

__global__ void count_kernel(const int* __restrict__ dst) {
    int e = blockIdx.x * blockDim.x + threadIdx.x;
    if (e < EE) atomicAdd(&g_cnt[dst[e]], 1);
}

__global__ void scan1_kernel() {
    __shared__ int ws[8];
    int i = blockIdx.x * 256 + threadIdx.x;
    int lane = threadIdx.x & 31, w = threadIdx.x >> 5;
    int v = (i < NN) ? g_cnt[i] : 0;
    int x = v;
    #pragma unroll
    for (int o = 1; o < 32; o <<= 1) {
        int y = __shfl_up_sync(0xffffffffu, x, o);
        if (lane >= o) x += y;
    }
    if (lane == 31) ws[w] = x;
    __syncthreads();
    if (w == 0 && lane < 8) {
        int s = ws[lane];
        #pragma unroll
        for (int o = 1; o < 8; o <<= 1) {
            int y = __shfl_up_sync(0x000000ffu, s, o);
            if (lane >= o) s += y;
        }
        ws[lane] = s;
    }
    __syncthreads();
    int incl = x + (w > 0 ? ws[w - 1] : 0);
    if (i < NN) g_rowptr[i] = incl - v;
    if (threadIdx.x == 255) g_bsum[blockIdx.x] = incl;
}

__global__ void scan2_kernel(int nb) {
    __shared__ int ws[8];
    int t = threadIdx.x, lane = t & 31, w = t >> 5;
    int v = (t < nb) ? g_bsum[t] : 0;
    int x = v;
    #pragma unroll
    for (int o = 1; o < 32; o <<= 1) {
        int y = __shfl_up_sync(0xffffffffu, x, o);
        if (lane >= o) x += y;
    }
    if (lane == 31) ws[w] = x;
    __syncthreads();
    if (w == 0 && lane < 8) {
        int s = ws[lane];
        #pragma unroll
        for (int o = 1; o < 8; o <<= 1) {
            int y = __shfl_up_sync(0x000000ffu, s, o);
            if (lane >= o) s += y;
        }
        ws[lane] = s;
    }
    __syncthreads();
    int incl = x + (w > 0 ? ws[w - 1] : 0);
    if (t < nb) g_bsum[t] = incl - v;
    if (t == nb - 1) g_rowptr[NN] = incl;
}

__global__ void scan3self_kernel() {
    int i = blockIdx.x * 256 + threadIdx.x;
    if (i < NN) {
        int r = g_rowptr[i] + g_bsum[i >> 8];
        g_rowptr[i] = r;
        g_col[r] = i;
        g_dstA[r] = i;
        g_cnt[i] = r + 1;
    }
}

__global__ void scatter_kernel(const int* __restrict__ src, const int* __restrict__ dst) {
    int e = blockIdx.x * blockDim.x + threadIdx.x;
    if (e < EE) {
        int d = dst[e];
        int p = atomicAdd(&g_cnt[d], 1);
        g_col[p] = src[e];
        g_dstA[p] = d;
    }
}

// ---------------- per-edge weight kernels ----------------
__global__ void weight1_kernel() {
    int j = blockIdx.x * 256 + threadIdx.x;
    if (j >= ET) return;
    int s = g_col[j], d = g_dstA[j];
    float4 as = *(const float4*)(g_as1 + s * 4);
    float4 ad = *(const float4*)(g_ad1 + d * 4);
    float4 w;
    w.x = __expf(lrelu(as.x + ad.x));
    w.y = __expf(lrelu(as.y + ad.y));
    w.z = __expf(lrelu(as.z + ad.z));
    w.w = __expf(lrelu(as.w + ad.w));
    *(float4*)(g_w1 + (size_t)j * 4) = w;
}

__global__ void weight2_kernel() {
    int j = blockIdx.x * 256 + threadIdx.x;
    if (j >= ET) return;
    g_w2[j] = __expf(lrelu(g_as2[g_col[j]] + g_ad2[g_dstA[j]]));
}

// ---------------- GEMM1 (mma.sync tf32) + fused alpha1, fp16 h1 output ----------------
#define G1_STRIDE 20

__device__ __forceinline__ void mma_tf32(float* c, const uint32_t* a, const uint32_t* b) {
    asm volatile(
        "mma.sync.aligned.m16n8k8.row.col.f32.tf32.tf32.f32 "
        "{%0,%1,%2,%3}, {%4,%5,%6,%7}, {%8,%9}, {%0,%1,%2,%3};"
        : "+f"(c[0]), "+f"(c[1]), "+f"(c[2]), "+f"(c[3])
        : "r"(a[0]), "r"(a[1]), "r"(a[2]), "r"(a[3]), "r"(b[0]), "r"(b[1]));
}

__global__ void __launch_bounds__(256) gemm1_mma_kernel(const float* __restrict__ x,
                                                        const float* __restrict__ as1,
                                                        const float* __restrict__ ad1) {
    __shared__ float sA[2][128 * G1_STRIDE];
    __shared__ float sB[2][128 * G1_STRIDE];

    int tid  = threadIdx.x;
    int wid  = tid >> 5, lane = tid & 31;
    int qr   = lane >> 2, qc = lane & 3;
    int warpM = (wid & 3) * 32;
    int warpN = (wid >> 2) * 64;
    int row0 = blockIdx.x * 128, col0 = blockIdx.y * 128;

    float c[2][8][4];
    #pragma unroll
    for (int mt = 0; mt < 2; mt++)
        #pragma unroll
        for (int nt = 0; nt < 8; nt++)
            #pragma unroll
            for (int i = 0; i < 4; i++) c[mt][nt][i] = 0.f;

    int lr  = tid >> 2;
    int lk4 = (tid & 3) * 4;

    {
        #pragma unroll
        for (int i = 0; i < 2; i++) {
            int r = lr + i * 64;
            int gr = row0 + r;
            float4 v = make_float4(0.f, 0.f, 0.f, 0.f);
            if (gr < NN) v = *(const float4*)(x + (size_t)gr * 256 + lk4);
            uint4 tv;
            tv.x = tf32_rna(v.x); tv.y = tf32_rna(v.y);
            tv.z = tf32_rna(v.z); tv.w = tf32_rna(v.w);
            *(uint4*)(&sA[0][r * G1_STRIDE + lk4]) = tv;
            float4 wv = *(const float4*)(g_W1T + (size_t)(col0 + r) * 256 + lk4);
            *(float4*)(&sB[0][r * G1_STRIDE + lk4]) = wv;
        }
    }
    __syncthreads();

    #pragma unroll 1
    for (int kt = 0; kt < 16; kt++) {
        int cur = kt & 1;
        float4 av[2], bv[2];
        if (kt < 15) {
            #pragma unroll
            for (int i = 0; i < 2; i++) {
                int r = lr + i * 64;
                int gr = row0 + r;
                av[i] = make_float4(0.f, 0.f, 0.f, 0.f);
                if (gr < NN) av[i] = *(const float4*)(x + (size_t)gr * 256 + (kt + 1) * 16 + lk4);
                bv[i] = *(const float4*)(g_W1T + (size_t)(col0 + r) * 256 + (kt + 1) * 16 + lk4);
            }
        }
        #pragma unroll
        for (int ks = 0; ks < 2; ks++) {
            int kb = ks * 8;
            uint32_t a[2][4], b[8][2];
            #pragma unroll
            for (int mt = 0; mt < 2; mt++) {
                int base = (warpM + mt * 16 + qr) * G1_STRIDE + kb + qc;
                a[mt][0] = __float_as_uint(sA[cur][base]);
                a[mt][1] = __float_as_uint(sA[cur][base + 8 * G1_STRIDE]);
                a[mt][2] = __float_as_uint(sA[cur][base + 4]);
                a[mt][3] = __float_as_uint(sA[cur][base + 8 * G1_STRIDE + 4]);
            }
            #pragma unroll
            for (int nt = 0; nt < 8; nt++) {
                int bb = (warpN + nt * 8 + qr) * G1_STRIDE + kb + qc;
                b[nt][0] = __float_as_uint(sB[cur][bb]);
                b[nt][1] = __float_as_uint(sB[cur][bb + 4]);
            }
            #pragma unroll
            for (int mt = 0; mt < 2; mt++)
                #pragma unroll
                for (int nt = 0; nt < 8; nt++)
                    mma_tf32(c[mt][nt], a[mt], b[nt]);
        }
        if (kt < 15) {
            int nxt = 1 - cur;
            #pragma unroll
            for (int i = 0; i < 2; i++) {
                int r = lr + i * 64;
                uint4 tv;
                tv.x = tf32_rna(av[i].x); tv.y = tf32_rna(av[i].y);
                tv.z = tf32_rna(av[i].z); tv.w = tf32_rna(av[i].w);
                *(uint4*)(&sA[nxt][r * G1_STRIDE + lk4]) = tv;
                *(float4*)(&sB[nxt][r * G1_STRIDE + lk4]) = bv[i];
            }
            __syncthreads();
        }
    }

    // epilogue: store h1 as fp16
    #pragma unroll
    for (int mt = 0; mt < 2; mt++) {
        int r1 = row0 + warpM + mt * 16 + qr;
        int r2 = r1 + 8;
        #pragma unroll
        for (int nt = 0; nt < 8; nt++) {
            int cc = col0 + warpN + nt * 8 + qc * 2;
            if (r1 < NN)
                *(__half2*)(g_h1h + (size_t)r1 * 256 + cc) = __floats2half2_rn(c[mt][nt][0], c[mt][nt][1]);
            if (r2 < NN)
                *(__half2*)(g_h1h + (size_t)r2 * 256 + cc) = __floats2half2_rn(c[mt][nt][2], c[mt][nt][3]);
        }
    }

    // fused alpha1 (fp32 fragments, exact)
    int h = blockIdx.y * 2 + (wid >> 2);
    float asv[16], adv[16];
    #pragma unroll
    for (int nt = 0; nt < 8; nt++)
        #pragma unroll
        for (int i = 0; i < 2; i++) {
            int cl = nt * 8 + qc * 2 + i;
            asv[nt * 2 + i] = as1[h * 64 + cl];
            adv[nt * 2 + i] = ad1[h * 64 + cl];
        }
    #pragma unroll
    for (int mt = 0; mt < 2; mt++) {
        float ps1 = 0.f, pd1 = 0.f, ps2 = 0.f, pd2 = 0.f;
        #pragma unroll
        for (int nt = 0; nt < 8; nt++) {
            ps1 += c[mt][nt][0] * asv[nt * 2] + c[mt][nt][1] * asv[nt * 2 + 1];
            pd1 += c[mt][nt][0] * adv[nt * 2] + c[mt][nt][1] * adv[nt * 2 + 1];
            ps2 += c[mt][nt][2] * asv[nt * 2] + c[mt][nt][3] * asv[nt * 2 + 1];
            pd2 += c[mt][nt][2] * adv[nt * 2] + c[mt][nt][3] * adv[nt * 2 + 1];
        }
        #pragma unroll
        for (int o = 1; o <= 2; o <<= 1) {
            ps1 += __shfl_xor_sync(0xffffffffu, ps1, o);
            pd1 += __shfl_xor_sync(0xffffffffu, pd1, o);
            ps2 += __shfl_xor_sync(0xffffffffu, ps2, o);
            pd2 += __shfl_xor_sync(0xffffffffu, pd2, o);
        }
        if (qc == 0) {
            int r1 = row0 + warpM + mt * 16 + qr, r2 = r1 + 8;
            if (r1 < NN) { g_as1[r1 * 4 + h] = ps1; g_ad1[r1 * 4 + h] = pd1; }
            if (r2 < NN) { g_as1[r2 * 4 + h] = ps2; g_ad1[r2 * 4 + h] = pd2; }
        }
    }
}

// ---------------- layer1: aggregate with precomputed weights + bias + ELU ----------------
__device__ __forceinline__ void acc_edge1(float* acc, float w, uint4 p) {
    __half2* q = (__half2*)&p;
    #pragma unroll
    for (int i = 0; i < 4; i++) {
        float2 f = __half22float2(q[i]);
        acc[2 * i]     += w * f.x;
        acc[2 * i + 1] += w * f.y;
    }
}

__global__ void agg1_kernel(const float* __restrict__ b1) {
    int n    = (blockIdx.x * blockDim.x + threadIdx.x) >> 5;
    int lane = threadIdx.x & 31;
    if (n >= NN) return;
    int beg = g_rowptr[n], end = g_rowptr[n + 1];
    int h = lane >> 3;

    float dn = 0.f;
    float acc[8];
    #pragma unroll
    for (int i = 0; i < 8; i++) acc[i] = 0.f;

    int j = beg;
    for (; j + 4 <= end; j += 4) {
        int s0 = g_col[j],     s1 = g_col[j + 1];
        int s2 = g_col[j + 2], s3 = g_col[j + 3];
        float w0 = g_w1[(size_t)(j)     * 4 + h];
        float w1 = g_w1[(size_t)(j + 1) * 4 + h];
        float w2 = g_w1[(size_t)(j + 2) * 4 + h];
        float w3 = g_w1[(size_t)(j + 3) * 4 + h];
        uint4 p0 = *(const uint4*)(g_h1h + (size_t)s0 * 256 + lane * 8);
        uint4 p1 = *(const uint4*)(g_h1h + (size_t)s1 * 256 + lane * 8);
        uint4 p2 = *(const uint4*)(g_h1h + (size_t)s2 * 256 + lane * 8);
        uint4 p3 = *(const uint4*)(g_h1h + (size_t)s3 * 256 + lane * 8);
        dn += (w0 + w1) + (w2 + w3);
        acc_edge1(acc, w0, p0);
        acc_edge1(acc, w1, p1);
        acc_edge1(acc, w2, p2);
        acc_edge1(acc, w3, p3);
    }
    for (; j < end; j++) {
        int s0 = g_col[j];
        float w0 = g_w1[(size_t)j * 4 + h];
        uint4 p0 = *(const uint4*)(g_h1h + (size_t)s0 * 256 + lane * 8);
        dn += w0;
        acc_edge1(acc, w0, p0);
    }

    float ih = 1.0f / (dn + 1e-16f);
    float4 bb1 = *(const float4*)(b1 + lane * 8);
    float4 bb2 = *(const float4*)(b1 + lane * 8 + 4);
    float o0 = acc[0] * ih + bb1.x, o1 = acc[1] * ih + bb1.y;
    float o2 = acc[2] * ih + bb1.z, o3 = acc[3] * ih + bb1.w;
    float o4 = acc[4] * ih + bb2.x, o5 = acc[5] * ih + bb2.y;
    float o6 = acc[6] * ih + bb2.z, o7 = acc[7] * ih + bb2.w;
    o0 = o0 > 0.f ? o0 : expm1f(o0);  o1 = o1 > 0.f ? o1 : expm1f(o1);
    o2 = o2 > 0.f ? o2 : expm1f(o2);  o3 = o3 > 0.f ? o3 : expm1f(o3);
    o4 = o4 > 0.f ? o4 : expm1f(o4);  o5 = o5 > 0.f ? o5 : expm1f(o5);
    o6 = o6 > 0.f ? o6 : expm1f(o6);  o7 = o7 > 0.f ? o7 : expm1f(o7);
    uint4 pk;
    __half2* ph = (__half2*)&pk;
    ph[0] = __floats2half2_rn(o0, o1);
    ph[1] = __floats2half2_rn(o2, o3);
    ph[2] = __floats2half2_rn(o4, o5);
    ph[3] = __floats2half2_rn(o6, o7);
    *(uint4*)(g_out1h + (size_t)n * 256 + lane * 8) = pk;
}

// ---------------- GEMM2 (f32x2, fp16 input) + fused alpha2, fp16 h2 output ----------------
#define W2S 258
__global__ void gemm2_kernel(const float* __restrict__ B,
                             const float* __restrict__ asrc,
                             const float* __restrict__ adst) {
    __shared__ float sW[32 * W2S];    // W2 transposed: sW[c][k]
    __shared__ float sA[64][32];
    int t = threadIdx.x;
    for (int i = t; i < 8192; i += 256) {
        int c = i & 31, k = i >> 5;
        sW[c * W2S + k] = B[k * 32 + c];
    }
    __syncthreads();

    int row0 = blockIdx.x * 64;
    int lane = t & 31;
    int rg = t >> 5;
    float a2s = asrc[lane], a2d = adst[lane];
    ull acc2[8];
    #pragma unroll
    for (int i = 0; i < 8; i++) acc2[i] = 0ULL;

    int lrr = t >> 2;          // 0..63 (row)
    int lk8 = (t & 3) * 8;     // 0,8,16,24

    for (int k0 = 0; k0 < 256; k0 += 32) {
        __syncthreads();
        {
            int gr = row0 + lrr;
            uint4 v = make_uint4(0u, 0u, 0u, 0u);
            if (gr < NN) v = *(const uint4*)(g_out1h + (size_t)gr * 256 + k0 + lk8);
            __half2* q = (__half2*)&v;
            #pragma unroll
            for (int i = 0; i < 4; i++) {
                float2 f = __half22float2(q[i]);
                sA[lrr][lk8 + 2 * i]     = f.x;
                sA[lrr][lk8 + 2 * i + 1] = f.y;
            }
        }
        __syncthreads();
        #pragma unroll
        for (int kk = 0; kk < 32; kk += 2) {
            ull b2 = *(const ull*)(&sW[lane * W2S + k0 + kk]);
            #pragma unroll
            for (int i = 0; i < 8; i++) {
                ull a2 = *(const ull*)(&sA[rg * 8 + i][kk]);
                ffma2(acc2[i], a2, b2);
            }
        }
    }
    #pragma unroll
    for (int i = 0; i < 8; i++) {
        int r = row0 + rg * 8 + i;
        float2 p = *(float2*)(&acc2[i]);
        float v = p.x + p.y;
        if (r < NN) g_h2h[r * 32 + lane] = __float2half_rn(v);
        float ps = v * a2s, pd = v * a2d;
        #pragma unroll
        for (int o = 16; o; o >>= 1) {
            ps += __shfl_xor_sync(0xffffffffu, ps, o);
            pd += __shfl_xor_sync(0xffffffffu, pd, o);
        }
        if (lane == 0 && r < NN) { g_as2[r] = ps; g_ad2[r] = pd; }
    }
}

// ---------------- layer2: aggregate with precomputed weights (half-warp per edge) ----------------
__global__ void agg2_kernel(const float* __restrict__ b2, float* __restrict__ out) {
    int n    = (blockIdx.x * blockDim.x + threadIdx.x) >> 5;
    int lane = threadIdx.x & 31;
    if (n >= NN) return;
    int beg = g_rowptr[n], end = g_rowptr[n + 1];
    int half = lane >> 4;          // 0 or 1
    int c2 = lane & 15;            // column pair

    float dn = 0.f, a0 = 0.f, a1 = 0.f;
    int j = beg;
    #pragma unroll 2
    for (; j + 2 <= end; j += 2) {
        int idx = j + half;
        int s = g_col[idx];
        float w = g_w2[idx];
        __half2 hv = *(const __half2*)(g_h2h + (size_t)s * 32 + c2 * 2);
        float2 f = __half22float2(hv);
        dn += w; a0 += w * f.x; a1 += w * f.y;
    }
    if (j < end && half == 0) {
        int s = g_col[j];
        float w = g_w2[j];
        __half2 hv = *(const __half2*)(g_h2h + (size_t)s * 32 + c2 * 2);
        float2 f = __half22float2(hv);
        dn += w; a0 += w * f.x; a1 += w * f.y;
    }
    dn += __shfl_xor_sync(0xffffffffu, dn, 16);
    a0 += __shfl_xor_sync(0xffffffffu, a0, 16);
    a1 += __shfl_xor_sync(0xffffffffu, a1, 16);
    if (half == 0) {
        float ih = 1.0f / (dn + 1e-16f);
        float2 o;
        o.x = a0 * ih + b2[c2 * 2];
        o.y = a1 * ih + b2[c2 * 2 + 1];
        *(float2*)(out + (size_t)n * 32 + c2 * 2) = o;
    }
}

// ---------------- launch ----------------
extern "C" void kernel_launch(void* const* d_in, const int* in_sizes, int n_in,
                              void* d_out, int out_size) {
    const float* x   = (const float*)d_in[0];
    const int*   ei  = (const int*)  d_in[1];
    const float* W1  = (const float*)d_in[2];
    const float* as1 = (const float*)d_in[3];
    const float* ad1 = (const float*)d_in[4];
    const float* b1  = (const float*)d_in[5];
    const float* W2  = (const float*)d_in[6];
    const float* as2 = (const float*)d_in[7];
    const float* ad2 = (const float*)d_in[8];
    const float* b2  = (const float*)d_in[9];
    float* out = (float*)d_out;

    const int* src = ei;
    const int* dst = ei + EE;

    int nb = (NN + 255) / 256;   // 196
    int eb = (ET + 255) / 256;   // 3321

    // fork a worker stream: gemm1 path runs concurrently with the CSR build
    cudaStream_t sB;
    cudaStreamCreate(&sB);
    cudaEvent_t evF, evJ;
    cudaEventCreateWithFlags(&evF, cudaEventDisableTiming);
    cudaEventCreateWithFlags(&evJ, cudaEventDisableTiming);

    cudaEventRecord(evF, 0);
    cudaStreamWaitEvent(sB, evF, 0);
    w1t_kernel<<<256, 256, 0, sB>>>(W1);
    dim3 g1((NN + 127) / 128, 2);
    gemm1_mma_kernel<<<g1, 256, 0, sB>>>(x, as1, ad1);
    cudaEventRecord(evJ, sB);

    // CSR build on the origin stream (overlaps with gemm1)
    init_cnt_kernel<<<nb, 256>>>();
    count_kernel<<<(EE + 255) / 256, 256>>>(dst);
    scan1_kernel<<<nb, 256>>>();
    scan2_kernel<<<1, 256>>>(nb);
    scan3self_kernel<<<nb, 256>>>();
    scatter_kernel<<<(EE + 255) / 256, 256>>>(src, dst);

    // join: weights need CSR + gemm1
    cudaStreamWaitEvent(0, evJ, 0);

    int warp_blocks = (NN * 32 + 255) / 256;
    weight1_kernel<<<eb, 256>>>();
    agg1_kernel<<<warp_blocks, 256>>>(b1);
    gemm2_kernel<<<(NN + 63) / 64, 256>>>(W2, as2, ad2);
    weight2_kernel<<<eb, 256>>>();
    agg2_kernel<<<warp_blocks, 256>>>(b2, out);
    // note: sB/evF/evJ intentionally not destroyed here — they may be
    // referenced by an in-progress stream capture; handles are tiny.
}